// round 14
// baseline (speedup 1.0000x reference)
#include <cuda_runtime.h>
#include <math.h>

#define NPC 16384
#define NTC 131072
#define NFC 131072
#define EC  262144
#define BC  256
#define FULLMASK 0xffffffffu

// ---------------- device scratch ----------------
__device__ float g_xp[NPC * 64];
__device__ float g_xt[2][NTC * 64];
__device__ float g_xf[2][NFC * 64];
__device__ float g_ap[NPC * 64];
__device__ float g_hs0[2][NPC * 64];
__device__ float g_hs1[2][NPC * 64];
__device__ float g_ss_pt[2][NPC], g_ss_pf[2][NPC], g_sd_tp[2][NPC], g_sd_fp[2][NPC];
__device__ float g_ss_tp[2][NTC], g_sd_pt[2][NTC];
__device__ float g_ss_fp[2][NFC], g_sd_pf[2][NFC];
__device__ float g_wsv[5 * 4 * 64], g_wdv[5 * 4 * 64];
__device__ int g_rp_pt[NTC + 1], g_rp_pf[NFC + 1];
__device__ int g_rp_tp[NPC + 1], g_rp_fp[NPC + 1];
__device__ int g_cs_pt[EC], g_cs_tp[EC], g_cs_pf[EC], g_cs_fp[EC];
__device__ int g_cnt[4 * NTC];
__device__ int g_aux[520];
__device__ float g_ra[NPC * 2];
__device__ float g_rep[BC * 576];
__device__ float g_h1[BC * 64], g_h2[BC * 64];

// ---------------- batched CSR build ----------------
__global__ void zero4(int* c) {
    int i = blockIdx.x * blockDim.x + threadIdx.x;
    if (i < 4 * NTC) c[i] = 0;
}

__global__ void hist4(const int* __restrict__ d0, const int* __restrict__ d1,
                      const int* __restrict__ d2, const int* __restrict__ d3,
                      int* __restrict__ cnt) {
    int t = blockIdx.y;
    const int* d = (t == 0) ? d0 : (t == 1) ? d1 : (t == 2) ? d2 : d3;
    int* c = cnt + t * NTC;
    int i = blockIdx.x * blockDim.x + threadIdx.x;
    if (i < EC) atomicAdd(&c[d[i]], 1);
}

__global__ void __launch_bounds__(1024) scanA(const int* __restrict__ cnt,
        int* rp0, int* rp1, int* rp2, int* rp3, int* __restrict__ aux) {
    __shared__ int ws[32];
    int t = blockIdx.y;
    int* rowptr = (t == 0) ? rp0 : (t == 1) ? rp1 : (t == 2) ? rp2 : rp3;
    int n = (t == 0) ? NTC : (t == 1) ? NPC : (t == 2) ? NFC : NPC;
    const int* deg = cnt + t * NTC;
    int tid = threadIdx.x, lane = tid & 31, wid = tid >> 5;
    int i = blockIdx.x * 1024 + tid;
    int v = (i < n) ? deg[i] : 0;
    int x = v;
    #pragma unroll
    for (int off = 1; off < 32; off <<= 1) {
        int y = __shfl_up_sync(FULLMASK, x, off);
        if (lane >= off) x += y;
    }
    if (lane == 31) ws[wid] = x;
    __syncthreads();
    if (tid < 32) {
        int s = ws[tid];
        #pragma unroll
        for (int off = 1; off < 32; off <<= 1) {
            int y = __shfl_up_sync(FULLMASK, s, off);
            if (tid >= off) s += y;
        }
        ws[tid] = s;
    }
    __syncthreads();
    int excl = x - v + (wid ? ws[wid - 1] : 0);
    if (i < n) rowptr[i] = excl;
    if (tid == 0) aux[t * 128 + blockIdx.x] = ws[31];
}

__global__ void __launch_bounds__(512) scanB(int* __restrict__ aux) {
    __shared__ int wsum[16];
    int tid = threadIdx.x;
    int t = tid >> 7, idx = tid & 127;
    int lane = tid & 31, wid = tid >> 5;
    int v = aux[t * 128 + idx];
    int x = v;
    #pragma unroll
    for (int off = 1; off < 32; off <<= 1) {
        int y = __shfl_up_sync(FULLMASK, x, off);
        if (lane >= off) x += y;
    }
    if (lane == 31) wsum[wid] = x;
    __syncthreads();
    int offsum = 0;
    for (int w = t * 4; w < wid; w++) offsum += wsum[w];
    int excl = x - v + offsum;
    aux[t * 128 + idx] = excl;
    if (idx == 127) aux[512 + t] = excl + v;
}

__global__ void __launch_bounds__(1024) scanC(int* __restrict__ cnt,
        int* rp0, int* rp1, int* rp2, int* rp3, const int* __restrict__ aux) {
    int t = blockIdx.y;
    int* rowptr = (t == 0) ? rp0 : (t == 1) ? rp1 : (t == 2) ? rp2 : rp3;
    int n = (t == 0) ? NTC : (t == 1) ? NPC : (t == 2) ? NFC : NPC;
    int i = blockIdx.x * 1024 + threadIdx.x;
    if (i < n) {
        rowptr[i] += aux[t * 128 + blockIdx.x];
        cnt[t * NTC + i] = 0;
    }
    if (i == 0) rowptr[n] = aux[512 + t];
}

__global__ void scatter4(const int* __restrict__ s0, const int* __restrict__ d0,
                         const int* __restrict__ s1, const int* __restrict__ d1,
                         const int* __restrict__ s2, const int* __restrict__ d2,
                         const int* __restrict__ s3, const int* __restrict__ d3,
                         const int* rp0, const int* rp1, const int* rp2, const int* rp3,
                         int* __restrict__ cnt,
                         int* c0, int* c1, int* c2, int* c3) {
    int t = blockIdx.y;
    const int* src = (t == 0) ? s0 : (t == 1) ? s1 : (t == 2) ? s2 : s3;
    const int* dst = (t == 0) ? d0 : (t == 1) ? d1 : (t == 2) ? d2 : d3;
    const int* rp  = (t == 0) ? rp0 : (t == 1) ? rp1 : (t == 2) ? rp2 : rp3;
    int* csr = (t == 0) ? c0 : (t == 1) ? c1 : (t == 2) ? c2 : c3;
    int* cur = cnt + t * NTC;
    int i = blockIdx.x * blockDim.x + threadIdx.x;
    if (i >= EC) return;
    int d = dst[i];
    int pos = rp[d] + atomicAdd(&cur[d], 1);
    csr[pos] = src[i];
}

// ---------------- score vectors for ALL layers ----------------
__global__ void vec_all(const float* __restrict__ Ws, const float* __restrict__ as,
                        const float* __restrict__ Wd, const float* __restrict__ ad,
                        float* __restrict__ wsv, float* __restrict__ wdv) {
    int idx = blockIdx.x * blockDim.x + threadIdx.x;
    if (idx >= 2 * 5 * 4 * 64) return;
    int which = idx >= 1280;
    int r = which ? idx - 1280 : idx;
    int i = r & 63, lt = r >> 6;
    const float* W = which ? Wd : Ws;
    const float* a = which ? ad : as;
    float* o = which ? wdv : wsv;
    float acc = 0.f;
    const float* wr = W + (size_t)(lt * 64 + i) * 64;
    const float* ar = a + lt * 64;
    #pragma unroll 8
    for (int j = 0; j < 64; j++) acc = fmaf(wr[j], ar[j], acc);
    o[r] = acc;
}

// ---------------- embed ----------------
__global__ void embed_k(const float* __restrict__ mass, const int* __restrict__ pstate,
                        const float* __restrict__ embW, const float* __restrict__ embS,
                        float* __restrict__ xp) {
    int idx = blockIdx.x * blockDim.x + threadIdx.x;
    if (idx >= NPC * 64) return;
    int n = idx >> 6, j = idx & 63;
    float v;
    if (j < 32) v = mass[n] * embW[j];
    else {
        int st = pstate[2 * n] + 2 * pstate[2 * n + 1];
        v = embS[st * 32 + (j - 32)];
    }
    xp[idx] = v;
}

// ---------------- up to 4 per-row dot products (layer-0 init) ----------------
__global__ void dot4(const float* __restrict__ X, int n,
                     const float* v0, float* o0, const float* v1, float* o1,
                     const float* v2, float* o2, const float* v3, float* o3) {
    int idx = blockIdx.x * blockDim.x + threadIdx.x;
    int w = idx >> 5;
    if (w >= n) return;
    int lane = idx & 31;
    float2 x = *(const float2*)&X[(size_t)w * 64 + lane * 2];
#define DODOT(v, o) if (v) { \
        float s = x.x * v[2 * lane] + x.y * v[2 * lane + 1]; \
        for (int off = 16; off; off >>= 1) s += __shfl_xor_sync(FULLMASK, s, off); \
        if (lane == 0) o[w] = s; }
    DODOT(v0, o0)
    DODOT(v1, o1)
    DODOT(v2, o2)
    DODOT(v3, o3)
#undef DODOT
}

// ---------------- bootstrap hs matmul ----------------
__global__ void __launch_bounds__(256) mm_hs(const float* __restrict__ X,
                                             const float* __restrict__ W0, float* __restrict__ Y0,
                                             const float* __restrict__ W1, float* __restrict__ Y1) {
    __shared__ float Xs[64][65];
    __shared__ float Wsh[64][68];
    int half = blockIdx.x >= (NPC / 64);
    int row0 = (half ? blockIdx.x - NPC / 64 : blockIdx.x) * 64;
    const float* W = half ? W1 : W0;
    float* Y = half ? Y1 : Y0;
    int tid = threadIdx.x;
    const float4* W4 = (const float4*)W;
    for (int i = tid; i < 1024; i += 256) {
        float4 v = W4[i];
        int r = i >> 4, c = (i & 15) * 4;
        Wsh[r][c] = v.x; Wsh[r][c + 1] = v.y; Wsh[r][c + 2] = v.z; Wsh[r][c + 3] = v.w;
    }
    const float4* X4 = (const float4*)(X + (size_t)row0 * 64);
    for (int i = tid; i < 1024; i += 256) {
        float4 v = X4[i];
        int r = i >> 4, c = (i & 15) * 4;
        Xs[r][c] = v.x; Xs[r][c + 1] = v.y; Xs[r][c + 2] = v.z; Xs[r][c + 3] = v.w;
    }
    __syncthreads();
    int tx = tid & 15, ty = tid >> 4;
    int c0 = tx * 4, r0 = ty * 4;
    float acc[4][4] = {};
    #pragma unroll
    for (int k = 0; k < 64; k++) {
        float4 w = *(const float4*)&Wsh[k][c0];
        float x0 = Xs[r0][k], x1 = Xs[r0 + 1][k], x2 = Xs[r0 + 2][k], x3 = Xs[r0 + 3][k];
        acc[0][0] = fmaf(x0, w.x, acc[0][0]); acc[0][1] = fmaf(x0, w.y, acc[0][1]);
        acc[0][2] = fmaf(x0, w.z, acc[0][2]); acc[0][3] = fmaf(x0, w.w, acc[0][3]);
        acc[1][0] = fmaf(x1, w.x, acc[1][0]); acc[1][1] = fmaf(x1, w.y, acc[1][1]);
        acc[1][2] = fmaf(x1, w.z, acc[1][2]); acc[1][3] = fmaf(x1, w.w, acc[1][3]);
        acc[2][0] = fmaf(x2, w.x, acc[2][0]); acc[2][1] = fmaf(x2, w.y, acc[2][1]);
        acc[2][2] = fmaf(x2, w.z, acc[2][2]); acc[2][3] = fmaf(x2, w.w, acc[2][3]);
        acc[3][0] = fmaf(x3, w.x, acc[3][0]); acc[3][1] = fmaf(x3, w.y, acc[3][1]);
        acc[3][2] = fmaf(x3, w.z, acc[3][2]); acc[3][3] = fmaf(x3, w.w, acc[3][3]);
    }
    #pragma unroll
    for (int i = 0; i < 4; i++)
        *(float4*)&Y[((size_t)(row0 + r0 + i)) * 64 + c0] =
            make_float4(acc[i][0], acc[i][1], acc[i][2], acc[i][3]);
}

// ================== MEGA: p-dst GAT (32 rows, 16 lanes/row) + t/f agg in one launch ==========
__global__ void __launch_bounds__(512, 2) mega(
        int npBlocks, int ntfA,
        const int* rp1, const int* cs1, const float* ss1, const float* sd1,
        const float* X1, const float* W1,
        const int* rp2, const int* cs2, const float* ss2, const float* sd2,
        const float* X2, const float* W2,
        const float* b1, const float* b2, float* Yp, int relu,
        const float* pv0, float* po0, const float* pv1, float* po1,
        const float* pv2, float* po2, const float* pv3, float* po3,
        const float* Wn0, float* hsOut0, const float* Wn1, float* hsOut1,
        const int* rpA, const int* csA, const float* ssA, const float* sdA,
        const float* hsA, const float* bA, float* YA,
        const float* vA0, float* oA0, const float* vA1, float* oA1,
        const int* rpB, const int* csB, const float* ssB, const float* sdB,
        const float* hsB, const float* bB, float* YB,
        const float* vB0, float* oB0, const float* vB1, float* oB1) {
    __shared__ float Zs[32 * 68];
    __shared__ float Wsh[64][68];
    int tid = threadIdx.x;

    if ((int)blockIdx.x < npBlocks) {
        // ---------------- p-part: 32 rows, 16 lanes/row (4 col x 4 edge-subgroups) ----------
        int row0 = blockIdx.x * 32;
        int g16 = tid >> 4, l16 = tid & 15;
        int gl = l16 & 3, sg = l16 >> 2;
        int tx = tid & 15, ty = tid >> 4;       // matmul: 1 row x 4 cols per thread
        int c0 = tx * 4;
        float acc[4] = {};
        int d = row0 + g16;
        for (int p = 0; p < 2; p++) {
            const int* rp = p ? rp2 : rp1;
            const int* cs = p ? cs2 : cs1;
            const float* ss = p ? ss2 : ss1;
            const float* sd = p ? sd2 : sd1;
            const float* X = p ? X2 : X1;
            const float* W = p ? W2 : W1;
            const float4* W4 = (const float4*)W;
            for (int i = tid; i < 1024; i += 512) {
                float4 v = W4[i];
                int r = i >> 4, c = (i & 15) * 4;
                Wsh[r][c] = v.x; Wsh[r][c + 1] = v.y; Wsh[r][c + 2] = v.z; Wsh[r][c + 3] = v.w;
            }
            int beg = rp[d], end = rp[d + 1];
            float sdv = sd[d];
            float m = -1e30f;
            for (int j = beg + l16; j < end; j += 16) {
                float t = ss[cs[j]] + sdv;
                t = t > 0.f ? t : 0.2f * t;
                m = fmaxf(m, t);
            }
            m = fmaxf(m, __shfl_xor_sync(FULLMASK, m, 1));
            m = fmaxf(m, __shfl_xor_sync(FULLMASK, m, 2));
            m = fmaxf(m, __shfl_xor_sync(FULLMASK, m, 4));
            m = fmaxf(m, __shfl_xor_sync(FULLMASK, m, 8));
            float s = 0.f;
            float4 a0 = {0,0,0,0}, a1 = {0,0,0,0}, a2 = {0,0,0,0}, a3 = {0,0,0,0};
            const float4* H4 = (const float4*)X;
            #pragma unroll 2
            for (int j = beg + sg; j < end; j += 4) {
                int src = cs[j];
                float t = ss[src] + sdv;
                t = t > 0.f ? t : 0.2f * t;
                float ex = __expf(t - m);
                s += ex;
                size_t hb = (size_t)src * 16 + gl * 4;
                float4 h0 = H4[hb], h1 = H4[hb + 1], h2 = H4[hb + 2], h3 = H4[hb + 3];
                a0.x = fmaf(ex, h0.x, a0.x); a0.y = fmaf(ex, h0.y, a0.y);
                a0.z = fmaf(ex, h0.z, a0.z); a0.w = fmaf(ex, h0.w, a0.w);
                a1.x = fmaf(ex, h1.x, a1.x); a1.y = fmaf(ex, h1.y, a1.y);
                a1.z = fmaf(ex, h1.z, a1.z); a1.w = fmaf(ex, h1.w, a1.w);
                a2.x = fmaf(ex, h2.x, a2.x); a2.y = fmaf(ex, h2.y, a2.y);
                a2.z = fmaf(ex, h2.z, a2.z); a2.w = fmaf(ex, h2.w, a2.w);
                a3.x = fmaf(ex, h3.x, a3.x); a3.y = fmaf(ex, h3.y, a3.y);
                a3.z = fmaf(ex, h3.z, a3.z); a3.w = fmaf(ex, h3.w, a3.w);
            }
            // merge the 4 edge-subgroups (lanes differing in bits 2,3)
            #pragma unroll
            for (int o = 4; o <= 8; o <<= 1) {
                s += __shfl_xor_sync(FULLMASK, s, o);
                a0.x += __shfl_xor_sync(FULLMASK, a0.x, o); a0.y += __shfl_xor_sync(FULLMASK, a0.y, o);
                a0.z += __shfl_xor_sync(FULLMASK, a0.z, o); a0.w += __shfl_xor_sync(FULLMASK, a0.w, o);
                a1.x += __shfl_xor_sync(FULLMASK, a1.x, o); a1.y += __shfl_xor_sync(FULLMASK, a1.y, o);
                a1.z += __shfl_xor_sync(FULLMASK, a1.z, o); a1.w += __shfl_xor_sync(FULLMASK, a1.w, o);
                a2.x += __shfl_xor_sync(FULLMASK, a2.x, o); a2.y += __shfl_xor_sync(FULLMASK, a2.y, o);
                a2.z += __shfl_xor_sync(FULLMASK, a2.z, o); a2.w += __shfl_xor_sync(FULLMASK, a2.w, o);
                a3.x += __shfl_xor_sync(FULLMASK, a3.x, o); a3.y += __shfl_xor_sync(FULLMASK, a3.y, o);
                a3.z += __shfl_xor_sync(FULLMASK, a3.z, o); a3.w += __shfl_xor_sync(FULLMASK, a3.w, o);
            }
            float inv = s > 0.f ? 1.f / s : 0.f;
            if (sg == 0) {
                float4* Zr = (float4*)&Zs[g16 * 68];
                Zr[gl * 4]     = make_float4(a0.x * inv, a0.y * inv, a0.z * inv, a0.w * inv);
                Zr[gl * 4 + 1] = make_float4(a1.x * inv, a1.y * inv, a1.z * inv, a1.w * inv);
                Zr[gl * 4 + 2] = make_float4(a2.x * inv, a2.y * inv, a2.z * inv, a2.w * inv);
                Zr[gl * 4 + 3] = make_float4(a3.x * inv, a3.y * inv, a3.z * inv, a3.w * inv);
            }
            __syncthreads();
            #pragma unroll
            for (int k = 0; k < 64; k++) {
                float4 wv = *(const float4*)&Wsh[k][c0];
                float x0 = Zs[ty * 68 + k];
                acc[0] = fmaf(x0, wv.x, acc[0]); acc[1] = fmaf(x0, wv.y, acc[1]);
                acc[2] = fmaf(x0, wv.z, acc[2]); acc[3] = fmaf(x0, wv.w, acc[3]);
            }
            __syncthreads();
        }
        // bias + relu, stage to Zs
        #pragma unroll
        for (int c = 0; c < 4; c++) {
            float v = acc[c] + b1[c0 + c] + b2[c0 + c];
            if (relu) v = fmaxf(v, 0.f);
            Zs[ty * 68 + c0 + c] = v;
        }
        __syncthreads();
        float4 ot = ((const float4*)&Zs[g16 * 68])[l16];
        ((float4*)&Yp[(size_t)d * 64])[l16] = ot;
#define PDOT(v, o) if (v) { \
        float4 vv = ((const float4*)v)[l16]; \
        float dd = ot.x * vv.x + ot.y * vv.y + ot.z * vv.z + ot.w * vv.w; \
        dd += __shfl_xor_sync(FULLMASK, dd, 1); \
        dd += __shfl_xor_sync(FULLMASK, dd, 2); \
        dd += __shfl_xor_sync(FULLMASK, dd, 4); \
        dd += __shfl_xor_sync(FULLMASK, dd, 8); \
        if (l16 == 0) o[d] = dd; }
        PDOT(pv0, po0)
        PDOT(pv1, po1)
        PDOT(pv2, po2)
        PDOT(pv3, po3)
#undef PDOT
        // ---- hs epilogue: hs(l+1) = new_xp @ Wnext (Zs holds post-act xp rows) ----
        if (Wn0) {
            for (int p = 0; p < 2; p++) {
                const float* Wn = p ? Wn1 : Wn0;
                float* hsO = p ? hsOut1 : hsOut0;
                const float4* Wn4 = (const float4*)Wn;
                __syncthreads();
                for (int i = tid; i < 1024; i += 512) {
                    float4 v = Wn4[i];
                    int r = i >> 4, c = (i & 15) * 4;
                    Wsh[r][c] = v.x; Wsh[r][c + 1] = v.y; Wsh[r][c + 2] = v.z; Wsh[r][c + 3] = v.w;
                }
                __syncthreads();
                float ea[4] = {};
                #pragma unroll
                for (int k = 0; k < 64; k++) {
                    float4 wv = *(const float4*)&Wsh[k][c0];
                    float x0 = Zs[ty * 68 + k];
                    ea[0] = fmaf(x0, wv.x, ea[0]); ea[1] = fmaf(x0, wv.y, ea[1]);
                    ea[2] = fmaf(x0, wv.z, ea[2]); ea[3] = fmaf(x0, wv.w, ea[3]);
                }
                *(float4*)&hsO[((size_t)(row0 + ty)) * 64 + c0] =
                    make_float4(ea[0], ea[1], ea[2], ea[3]);
            }
        }
    } else {
        // ---------------- tf-part: 4 lanes/row, two-pass fixed-max ----------------
        int tfIdx = blockIdx.x - npBlocks;
        bool isA = tfIdx < ntfA;
        int row0 = (isA ? tfIdx : tfIdx - ntfA) * 128;
        const int* rp = isA ? rpA : rpB;
        const int* cs = isA ? csA : csB;
        const float* ss = isA ? ssA : ssB;
        const float* sd = isA ? sdA : sdB;
        const float* hs = isA ? hsA : hsB;
        const float* b = isA ? bA : bB;
        float* Y = isA ? YA : YB;
        const float* v0 = isA ? vA0 : vB0;  float* o0 = isA ? oA0 : oB0;
        const float* v1 = isA ? vA1 : vB1;  float* o1 = isA ? oA1 : oB1;

        int g = tid >> 2, gl = tid & 3;
        int d = row0 + g;
        int beg = rp[d], end = rp[d + 1];
        float sdv = sd[d];
        float m = -1e30f;
        for (int j = beg + gl; j < end; j += 4) {
            float t = ss[cs[j]] + sdv;
            t = t > 0.f ? t : 0.2f * t;
            m = fmaxf(m, t);
        }
        m = fmaxf(m, __shfl_xor_sync(FULLMASK, m, 1));
        m = fmaxf(m, __shfl_xor_sync(FULLMASK, m, 2));
        float s = 0.f;
        float4 a0 = {0,0,0,0}, a1 = {0,0,0,0}, a2 = {0,0,0,0}, a3 = {0,0,0,0};
        const float4* H4 = (const float4*)hs;
        #pragma unroll 2
        for (int j = beg; j < end; j++) {
            int src = cs[j];
            float t = ss[src] + sdv;
            t = t > 0.f ? t : 0.2f * t;
            float ex = __expf(t - m);
            s += ex;
            size_t hb = (size_t)src * 16 + gl * 4;
            float4 h0 = H4[hb], h1 = H4[hb + 1], h2 = H4[hb + 2], h3 = H4[hb + 3];
            a0.x = fmaf(ex, h0.x, a0.x); a0.y = fmaf(ex, h0.y, a0.y);
            a0.z = fmaf(ex, h0.z, a0.z); a0.w = fmaf(ex, h0.w, a0.w);
            a1.x = fmaf(ex, h1.x, a1.x); a1.y = fmaf(ex, h1.y, a1.y);
            a1.z = fmaf(ex, h1.z, a1.z); a1.w = fmaf(ex, h1.w, a1.w);
            a2.x = fmaf(ex, h2.x, a2.x); a2.y = fmaf(ex, h2.y, a2.y);
            a2.z = fmaf(ex, h2.z, a2.z); a2.w = fmaf(ex, h2.w, a2.w);
            a3.x = fmaf(ex, h3.x, a3.x); a3.y = fmaf(ex, h3.y, a3.y);
            a3.z = fmaf(ex, h3.z, a3.z); a3.w = fmaf(ex, h3.w, a3.w);
        }
        float inv = s > 0.f ? 1.f / s : 0.f;
        const float4* B4 = (const float4*)b;
        float4 bb0 = B4[gl * 4], bb1 = B4[gl * 4 + 1], bb2 = B4[gl * 4 + 2], bb3 = B4[gl * 4 + 3];
        float4 ot[4];
        ot[0] = make_float4(a0.x * inv + bb0.x, a0.y * inv + bb0.y, a0.z * inv + bb0.z, a0.w * inv + bb0.w);
        ot[1] = make_float4(a1.x * inv + bb1.x, a1.y * inv + bb1.y, a1.z * inv + bb1.z, a1.w * inv + bb1.w);
        ot[2] = make_float4(a2.x * inv + bb2.x, a2.y * inv + bb2.y, a2.z * inv + bb2.z, a2.w * inv + bb2.w);
        ot[3] = make_float4(a3.x * inv + bb3.x, a3.y * inv + bb3.y, a3.z * inv + bb3.z, a3.w * inv + bb3.w);
        if (relu) {
            #pragma unroll
            for (int q = 0; q < 4; q++) {
                ot[q].x = fmaxf(ot[q].x, 0.f); ot[q].y = fmaxf(ot[q].y, 0.f);
                ot[q].z = fmaxf(ot[q].z, 0.f); ot[q].w = fmaxf(ot[q].w, 0.f);
            }
        }
        float4* Yr = (float4*)&Y[(size_t)d * 64];
        #pragma unroll
        for (int q = 0; q < 4; q++) Yr[gl * 4 + q] = ot[q];
#define TDOT(v, o) { \
        const float4* V4 = (const float4*)v; \
        float dd = 0.f; \
        _Pragma("unroll") \
        for (int q = 0; q < 4; q++) { \
            float4 vv = V4[gl * 4 + q]; \
            dd += ot[q].x * vv.x + ot[q].y * vv.y + ot[q].z * vv.z + ot[q].w * vv.w; \
        } \
        dd += __shfl_xor_sync(FULLMASK, dd, 1); \
        dd += __shfl_xor_sync(FULLMASK, dd, 2); \
        if (gl == 0) o[d] = dd; }
        TDOT(v0, o0)
        TDOT(v1, o1)
#undef TDOT
    }
}

// ---------------- fused pooling: 3 tables in one launch ----------------
__global__ void pool3(const float* __restrict__ xp, const float* __restrict__ xt,
                      const float* __restrict__ xf, float* __restrict__ rep) {
    int which = blockIdx.y;
    const float* x = (which == 0) ? xp : (which == 1) ? xt : xf;
    int npg = (which == 0) ? 64 : 512;
    int off = which * 192;
    int b = blockIdx.x;
    int t = threadIdx.x;            // 256
    int d = t & 63, c = t >> 6;
    const float* base = x + (size_t)b * npg * 64;
    float mx = -1e30f, mn = 1e30f, sm = 0.f;
    for (int n = c; n < npg; n += 4) {
        float v = base[(size_t)n * 64 + d];
        mx = fmaxf(mx, v); mn = fminf(mn, v); sm += v;
    }
    __shared__ float smx[4][64], smn[4][64], ssm[4][64];
    smx[c][d] = mx; smn[c][d] = mn; ssm[c][d] = sm;
    __syncthreads();
    if (c == 0) {
        for (int i = 1; i < 4; i++) {
            mx = fmaxf(mx, smx[i][d]); mn = fminf(mn, smn[i][d]); sm += ssm[i][d];
        }
        rep[b * 576 + off + d] = mx;
        rep[b * 576 + off + 64 + d] = mn;
        rep[b * 576 + off + 128 + d] = sm / (float)npg;
    }
}

// ---------------- LayerNorm + out_a projection ----------------
__global__ void ln_ra(const float* __restrict__ ap, const float* __restrict__ g,
                      const float* __restrict__ be, const float* __restrict__ Wa,
                      const float* __restrict__ ba, float* __restrict__ ra) {
    int idx = blockIdx.x * blockDim.x + threadIdx.x;
    int n = idx >> 5;
    if (n >= NPC) return;
    int lane = idx & 31;
    float2 v = *(const float2*)&ap[(size_t)n * 64 + lane * 2];
    float sum = v.x + v.y;
    for (int o = 16; o; o >>= 1) sum += __shfl_xor_sync(FULLMASK, sum, o);
    float mu = sum * (1.f / 64.f);
    float dx = v.x - mu, dy = v.y - mu;
    float vs = dx * dx + dy * dy;
    for (int o = 16; o; o >>= 1) vs += __shfl_xor_sync(FULLMASK, vs, o);
    float rs = rsqrtf(vs * (1.f / 64.f) + 1e-5f);
    float y0 = dx * rs * g[2 * lane] + be[2 * lane];
    float y1 = dy * rs * g[2 * lane + 1] + be[2 * lane + 1];
    float r0 = y0 * Wa[(2 * lane) * 2]     + y1 * Wa[(2 * lane + 1) * 2];
    float r1 = y0 * Wa[(2 * lane) * 2 + 1] + y1 * Wa[(2 * lane + 1) * 2 + 1];
    for (int o = 16; o; o >>= 1) r0 += __shfl_xor_sync(FULLMASK, r0, o);
    for (int o = 16; o; o >>= 1) r1 += __shfl_xor_sync(FULLMASK, r1, o);
    if (lane == 0) {
        ra[2 * n]     = r0 + ba[0];
        ra[2 * n + 1] = r1 + ba[1];
    }
}

// ---------------- per-graph softmax + scatter to actions ----------------
__device__ __forceinline__ float blk64_max(float v, volatile float* sh) {
    for (int o = 16; o; o >>= 1) v = fmaxf(v, __shfl_xor_sync(FULLMASK, v, o));
    if ((threadIdx.x & 31) == 0) sh[threadIdx.x >> 5] = v;
    __syncthreads();
    float r = fmaxf(sh[0], sh[1]);
    __syncthreads();
    return r;
}
__device__ __forceinline__ float blk64_sum(float v, volatile float* sh) {
    for (int o = 16; o; o >>= 1) v += __shfl_xor_sync(FULLMASK, v, o);
    if ((threadIdx.x & 31) == 0) sh[threadIdx.x >> 5] = v;
    __syncthreads();
    float r = sh[0] + sh[1];
    __syncthreads();
    return r;
}

__global__ void act_softmax(const float* __restrict__ ra, const int* __restrict__ part_id,
                            float* __restrict__ out) {
    __shared__ float sh[2];
    int b = blockIdx.x, t = threadIdx.x;        // 64
    int n = b * 64 + t;
    float v0 = ra[2 * n], v1 = ra[2 * n + 1];
    float m0 = blk64_max(v0, sh);
    float m1 = blk64_max(v1, sh);
    float e0 = expf(v0 - m0), e1 = expf(v1 - m1);
    float s0 = blk64_sum(e0, sh);
    float s1 = blk64_sum(e1, sh);
    int p = part_id[n];
    out[b * 128 + p] = e0 / s0;
    out[b * 128 + 64 + p] = e1 / s1;
}

// ---------------- value head MLPs ----------------
__global__ void mlp_k(const float* __restrict__ in, int K, const float* __restrict__ W,
                      const float* __restrict__ bias, float* __restrict__ out) {
    __shared__ float s[576];
    int b = blockIdx.x, j = threadIdx.x;        // 64
    for (int k = j; k < K; k += 64) s[k] = in[b * K + k];
    __syncthreads();
    float acc = bias[j];
    for (int k = 0; k < K; k++) acc = fmaf(s[k], W[k * 64 + j], acc);
    acc = 0.5f * acc * (1.f + erff(acc * 0.70710678118654752f));
    out[b * 64 + j] = acc;
}

__global__ void mlp_out(const float* __restrict__ h, const float* __restrict__ Wo,
                        const float* __restrict__ bo, float* __restrict__ V) {
    int idx = blockIdx.x * blockDim.x + threadIdx.x;
    int b = idx >> 5;
    if (b >= BC) return;
    int lane = idx & 31;
    float2 v = *(const float2*)&h[b * 64 + lane * 2];
    float s = v.x * Wo[2 * lane] + v.y * Wo[2 * lane + 1];
    for (int o = 16; o; o >>= 1) s += __shfl_xor_sync(FULLMASK, s, o);
    if (lane == 0) V[b] = tanhf(s + bo[0]);
}

// ---------------- host ----------------
#define SYMF(p, s) do { void* _q; cudaGetSymbolAddress(&_q, s); p = (float*)_q; } while (0)
#define SYMI(p, s) do { void* _q; cudaGetSymbolAddress(&_q, s); p = (int*)_q; } while (0)

extern "C" void kernel_launch(void* const* d_in, const int* in_sizes, int n_in,
                              void* d_out, int out_size) {
    const float* mass      = (const float*)d_in[0];
    const int*   pstate    = (const int*)d_in[1];
    const float* torque_x  = (const float*)d_in[2];
    const float* force_x   = (const float*)d_in[3];
    const int* e_pt_src = (const int*)d_in[4];
    const int* e_pt_dst = (const int*)d_in[5];
    const int* e_tp_src = (const int*)d_in[6];
    const int* e_tp_dst = (const int*)d_in[7];
    const int* e_pf_src = (const int*)d_in[8];
    const int* e_pf_dst = (const int*)d_in[9];
    const int* e_fp_src = (const int*)d_in[10];
    const int* e_fp_dst = (const int*)d_in[11];
    const int* part_id  = (const int*)d_in[13];
    const float* embW   = (const float*)d_in[14];
    const float* embS   = (const float*)d_in[15];
    const float* W_src  = (const float*)d_in[16];
    const float* W_dst  = (const float*)d_in[17];
    const float* a_src  = (const float*)d_in[18];
    const float* a_dst  = (const float*)d_in[19];
    const float* b_conv = (const float*)d_in[20];
    const float* ln_g   = (const float*)d_in[21];
    const float* ln_b   = (const float*)d_in[22];
    const float* outaW  = (const float*)d_in[23];
    const float* outab  = (const float*)d_in[24];
    const float* innW   = (const float*)d_in[25];
    const float* innb   = (const float*)d_in[26];
    const float* fulW   = (const float*)d_in[27];
    const float* fulb   = (const float*)d_in[28];
    const float* outW   = (const float*)d_in[29];
    const float* outb   = (const float*)d_in[30];
    float* out = (float*)d_out;

    float *xp, *xt, *xf, *ap, *hs0, *hs1;
    float *ss_pt, *ss_pf, *sd_tp, *sd_fp, *ss_tp, *sd_pt, *ss_fp, *sd_pf;
    float *wsv, *wdv, *ra, *rep, *h1, *h2;
    int *rp_pt, *rp_pf, *rp_tp, *rp_fp, *cs_pt, *cs_tp, *cs_pf, *cs_fp, *cnt, *aux;
    SYMF(xp, g_xp); SYMF(xt, g_xt); SYMF(xf, g_xf); SYMF(ap, g_ap);
    SYMF(hs0, g_hs0); SYMF(hs1, g_hs1);
    SYMF(ss_pt, g_ss_pt); SYMF(ss_pf, g_ss_pf); SYMF(sd_tp, g_sd_tp); SYMF(sd_fp, g_sd_fp);
    SYMF(ss_tp, g_ss_tp); SYMF(sd_pt, g_sd_pt); SYMF(ss_fp, g_ss_fp); SYMF(sd_pf, g_sd_pf);
    SYMF(wsv, g_wsv); SYMF(wdv, g_wdv); SYMF(ra, g_ra);
    SYMF(rep, g_rep); SYMF(h1, g_h1); SYMF(h2, g_h2);
    SYMI(rp_pt, g_rp_pt); SYMI(rp_pf, g_rp_pf); SYMI(rp_tp, g_rp_tp); SYMI(rp_fp, g_rp_fp);
    SYMI(cs_pt, g_cs_pt); SYMI(cs_tp, g_cs_tp); SYMI(cs_pf, g_cs_pf); SYMI(cs_fp, g_cs_fp);
    SYMI(cnt, g_cnt); SYMI(aux, g_aux);

    // batched CSR build (parallel 3-phase scan)
    zero4<<<(4 * NTC) / 256, 256>>>(cnt);
    { dim3 g(EC / 256, 4); hist4<<<g, 256>>>(e_pt_dst, e_tp_dst, e_pf_dst, e_fp_dst, cnt); }
    { dim3 g(128, 4); scanA<<<g, 1024>>>(cnt, rp_pt, rp_tp, rp_pf, rp_fp, aux); }
    scanB<<<1, 512>>>(aux);
    { dim3 g(128, 4); scanC<<<g, 1024>>>(cnt, rp_pt, rp_tp, rp_pf, rp_fp, aux); }
    { dim3 g(EC / 256, 4);
      scatter4<<<g, 256>>>(e_pt_src, e_pt_dst, e_tp_src, e_tp_dst,
                           e_pf_src, e_pf_dst, e_fp_src, e_fp_dst,
                           rp_pt, rp_tp, rp_pf, rp_fp, cnt,
                           cs_pt, cs_tp, cs_pf, cs_fp); }

    // score vectors; embed; layer-0 score dots; bootstrap hs (parity 0)
    vec_all<<<10, 256>>>(W_src, a_src, W_dst, a_dst, wsv, wdv);
    dot4<<<(NTC * 32) / 256, 256>>>(torque_x, NTC,
         wsv + 1 * 64, ss_tp, wdv + 0 * 64, sd_pt, nullptr, nullptr, nullptr, nullptr);
    dot4<<<(NFC * 32) / 256, 256>>>(force_x, NFC,
         wsv + 3 * 64, ss_fp, wdv + 2 * 64, sd_pf, nullptr, nullptr, nullptr, nullptr);
    embed_k<<<(NPC * 64) / 256, 256>>>(mass, pstate, embW, embS, xp);
    dot4<<<(NPC * 32) / 256, 256>>>(xp, NPC,
         wsv + 0 * 64, ss_pt, wsv + 2 * 64, ss_pf,
         wdv + 1 * 64, sd_tp, wdv + 3 * 64, sd_fp);
    mm_hs<<<2 * (NPC / 64), 256>>>(xp, W_src + 0 * 4096, hs0, W_src + 2 * 4096, hs1);

    for (int l = 0; l < 5; l++) {
        int ci = l & 1, ni = (l + 1) & 1;
        const float* xti = (l == 0) ? torque_x : xt + (size_t)ni * NTC * 64;
        const float* xfi = (l == 0) ? force_x  : xf + (size_t)ni * NFC * 64;
        float* xto = xt + (size_t)ci * NTC * 64;
        float* xfo = xf + (size_t)ci * NFC * 64;
        const float* Wl = W_src + (size_t)l * 4 * 4096;
        const float* bl = b_conv + (size_t)l * 4 * 64;
        int relu = (l < 3) ? 1 : 0;
        int actor = (l == 4);
        const float* nwsv = wsv + (size_t)(l + 1) * 4 * 64;
        const float* nwdv = wdv + (size_t)(l + 1) * 4 * 64;
        const float* c_ss_pt = ss_pt + ci * NPC;  float* n_ss_pt = ss_pt + ni * NPC;
        const float* c_ss_pf = ss_pf + ci * NPC;  float* n_ss_pf = ss_pf + ni * NPC;
        const float* c_sd_tp = sd_tp + ci * NPC;  float* n_sd_tp = sd_tp + ni * NPC;
        const float* c_sd_fp = sd_fp + ci * NPC;  float* n_sd_fp = sd_fp + ni * NPC;
        const float* c_ss_tp = ss_tp + ci * NTC;  float* n_ss_tp = ss_tp + ni * NTC;
        const float* c_sd_pt = sd_pt + ci * NTC;  float* n_sd_pt = sd_pt + ni * NTC;
        const float* c_ss_fp = ss_fp + ci * NFC;  float* n_ss_fp = ss_fp + ni * NFC;
        const float* c_sd_pf = sd_pf + ci * NFC;  float* n_sd_pf = sd_pf + ni * NFC;
        const float* hs0c = hs0 + (size_t)ci * NPC * 64;
        const float* hs1c = hs1 + (size_t)ci * NPC * 64;
        float* hs0n = hs0 + (size_t)ni * NPC * 64;
        float* hs1n = hs1 + (size_t)ni * NPC * 64;
        const float* Wnext = W_src + (size_t)(l + 1) * 4 * 4096;
        int doEpi = (l < 3);

        if (!actor) {
            mega<<<NPC / 32 + NTC / 128 + NFC / 128, 512>>>(
                NPC / 32, NTC / 128,
                rp_tp, cs_tp, c_ss_tp, c_sd_tp, xti, Wl + 1 * 4096,
                rp_fp, cs_fp, c_ss_fp, c_sd_fp, xfi, Wl + 3 * 4096,
                bl + 1 * 64, bl + 3 * 64, xp, relu,
                nwsv + 0 * 64, n_ss_pt, nwsv + 2 * 64, n_ss_pf,
                nwdv + 1 * 64, n_sd_tp, nwdv + 3 * 64, n_sd_fp,
                doEpi ? (Wnext + 0 * 4096) : nullptr, hs0n,
                doEpi ? (Wnext + 2 * 4096) : nullptr, hs1n,
                rp_pt, cs_pt, c_ss_pt, c_sd_pt, hs0c, bl + 0 * 64, xto,
                nwsv + 1 * 64, n_ss_tp, nwdv + 0 * 64, n_sd_pt,
                rp_pf, cs_pf, c_ss_pf, c_sd_pf, hs1c, bl + 2 * 64, xfo,
                nwsv + 3 * 64, n_ss_fp, nwdv + 2 * 64, n_sd_pf);
        } else {
            mega<<<NPC / 32, 512>>>(
                NPC / 32, 0,
                rp_tp, cs_tp, c_ss_tp, c_sd_tp, xti, Wl + 1 * 4096,
                rp_fp, cs_fp, c_ss_fp, c_sd_fp, xfi, Wl + 3 * 4096,
                bl + 1 * 64, bl + 3 * 64, ap, 0,
                nullptr, nullptr, nullptr, nullptr,
                nullptr, nullptr, nullptr, nullptr,
                nullptr, nullptr, nullptr, nullptr,
                nullptr, nullptr, nullptr, nullptr, nullptr, nullptr, nullptr,
                nullptr, nullptr, nullptr, nullptr,
                nullptr, nullptr, nullptr, nullptr, nullptr, nullptr, nullptr,
                nullptr, nullptr, nullptr, nullptr);
        }
    }

    // fused pooling: l=3 wrote xt/xf parity 1; xp in place
    { dim3 g(BC, 3); pool3<<<g, 256>>>(xp, xt + (size_t)NTC * 64, xf + (size_t)NFC * 64, rep); }

    // actor head
    ln_ra<<<(NPC * 32) / 256, 256>>>(ap, ln_g, ln_b, outaW, outab, ra);
    act_softmax<<<BC, 64>>>(ra, part_id, out);

    // value head
    mlp_k<<<BC, 64>>>(rep, 576, innW, innb, h1);
    mlp_k<<<BC, 64>>>(h1, 64, fulW, fulb, h2);
    mlp_out<<<(BC * 32) / 256, 256>>>(h2, outW, outb, out + BC * 128);
}

// round 15
// speedup vs baseline: 1.1595x; 1.1595x over previous
#include <cuda_runtime.h>
#include <math.h>

#define NPC 16384
#define NTC 131072
#define NFC 131072
#define EC  262144
#define BC  256
#define FULLMASK 0xffffffffu

// ---------------- device scratch ----------------
__device__ float g_xp[NPC * 64];
__device__ float g_xt[2][NTC * 64];
__device__ float g_xf[2][NFC * 64];
__device__ float g_ap[NPC * 64];
__device__ float g_hs0[2][NPC * 64];
__device__ float g_hs1[2][NPC * 64];
__device__ float g_ss_pt[2][NPC], g_ss_pf[2][NPC], g_sd_tp[2][NPC], g_sd_fp[2][NPC];
__device__ float g_ss_tp[2][NTC], g_sd_pt[2][NTC];
__device__ float g_ss_fp[2][NFC], g_sd_pf[2][NFC];
__device__ float g_wsv[5 * 4 * 64], g_wdv[5 * 4 * 64];
__device__ int g_rp_pt[NTC + 1], g_rp_pf[NFC + 1];
__device__ int g_rp_tp[NPC + 1], g_rp_fp[NPC + 1];
__device__ int g_cs_pt[EC], g_cs_tp[EC], g_cs_pf[EC], g_cs_fp[EC];
__device__ int g_cnt[4 * NTC];
__device__ int g_aux[520];
__device__ float g_rep[BC * 576];

// ---------------- batched CSR build ----------------
__global__ void zero4(int* c) {
    int i = blockIdx.x * blockDim.x + threadIdx.x;
    if (i < 4 * NTC) c[i] = 0;
}

__global__ void hist4(const int* __restrict__ d0, const int* __restrict__ d1,
                      const int* __restrict__ d2, const int* __restrict__ d3,
                      int* __restrict__ cnt) {
    int t = blockIdx.y;
    const int* d = (t == 0) ? d0 : (t == 1) ? d1 : (t == 2) ? d2 : d3;
    int* c = cnt + t * NTC;
    int i = blockIdx.x * blockDim.x + threadIdx.x;
    if (i < EC) atomicAdd(&c[d[i]], 1);
}

__global__ void __launch_bounds__(1024) scanA(const int* __restrict__ cnt,
        int* rp0, int* rp1, int* rp2, int* rp3, int* __restrict__ aux) {
    __shared__ int ws[32];
    int t = blockIdx.y;
    int* rowptr = (t == 0) ? rp0 : (t == 1) ? rp1 : (t == 2) ? rp2 : rp3;
    int n = (t == 0) ? NTC : (t == 1) ? NPC : (t == 2) ? NFC : NPC;
    const int* deg = cnt + t * NTC;
    int tid = threadIdx.x, lane = tid & 31, wid = tid >> 5;
    int i = blockIdx.x * 1024 + tid;
    int v = (i < n) ? deg[i] : 0;
    int x = v;
    #pragma unroll
    for (int off = 1; off < 32; off <<= 1) {
        int y = __shfl_up_sync(FULLMASK, x, off);
        if (lane >= off) x += y;
    }
    if (lane == 31) ws[wid] = x;
    __syncthreads();
    if (tid < 32) {
        int s = ws[tid];
        #pragma unroll
        for (int off = 1; off < 32; off <<= 1) {
            int y = __shfl_up_sync(FULLMASK, s, off);
            if (tid >= off) s += y;
        }
        ws[tid] = s;
    }
    __syncthreads();
    int excl = x - v + (wid ? ws[wid - 1] : 0);
    if (i < n) rowptr[i] = excl;
    if (tid == 0) aux[t * 128 + blockIdx.x] = ws[31];
}

__global__ void __launch_bounds__(512) scanB(int* __restrict__ aux) {
    __shared__ int wsum[16];
    int tid = threadIdx.x;
    int t = tid >> 7, idx = tid & 127;
    int lane = tid & 31, wid = tid >> 5;
    int v = aux[t * 128 + idx];
    int x = v;
    #pragma unroll
    for (int off = 1; off < 32; off <<= 1) {
        int y = __shfl_up_sync(FULLMASK, x, off);
        if (lane >= off) x += y;
    }
    if (lane == 31) wsum[wid] = x;
    __syncthreads();
    int offsum = 0;
    for (int w = t * 4; w < wid; w++) offsum += wsum[w];
    int excl = x - v + offsum;
    aux[t * 128 + idx] = excl;
    if (idx == 127) aux[512 + t] = excl + v;
}

__global__ void __launch_bounds__(1024) scanC(int* __restrict__ cnt,
        int* rp0, int* rp1, int* rp2, int* rp3, const int* __restrict__ aux) {
    int t = blockIdx.y;
    int* rowptr = (t == 0) ? rp0 : (t == 1) ? rp1 : (t == 2) ? rp2 : rp3;
    int n = (t == 0) ? NTC : (t == 1) ? NPC : (t == 2) ? NFC : NPC;
    int i = blockIdx.x * 1024 + threadIdx.x;
    if (i < n) {
        rowptr[i] += aux[t * 128 + blockIdx.x];
        cnt[t * NTC + i] = 0;
    }
    if (i == 0) rowptr[n] = aux[512 + t];
}

__global__ void scatter4(const int* __restrict__ s0, const int* __restrict__ d0,
                         const int* __restrict__ s1, const int* __restrict__ d1,
                         const int* __restrict__ s2, const int* __restrict__ d2,
                         const int* __restrict__ s3, const int* __restrict__ d3,
                         const int* rp0, const int* rp1, const int* rp2, const int* rp3,
                         int* __restrict__ cnt,
                         int* c0, int* c1, int* c2, int* c3) {
    int t = blockIdx.y;
    const int* src = (t == 0) ? s0 : (t == 1) ? s1 : (t == 2) ? s2 : s3;
    const int* dst = (t == 0) ? d0 : (t == 1) ? d1 : (t == 2) ? d2 : d3;
    const int* rp  = (t == 0) ? rp0 : (t == 1) ? rp1 : (t == 2) ? rp2 : rp3;
    int* csr = (t == 0) ? c0 : (t == 1) ? c1 : (t == 2) ? c2 : c3;
    int* cur = cnt + t * NTC;
    int i = blockIdx.x * blockDim.x + threadIdx.x;
    if (i >= EC) return;
    int d = dst[i];
    int pos = rp[d] + atomicAdd(&cur[d], 1);
    csr[pos] = src[i];
}

// ---------------- score vectors for ALL layers ----------------
__global__ void vec_all(const float* __restrict__ Ws, const float* __restrict__ as,
                        const float* __restrict__ Wd, const float* __restrict__ ad,
                        float* __restrict__ wsv, float* __restrict__ wdv) {
    int idx = blockIdx.x * blockDim.x + threadIdx.x;
    if (idx >= 2 * 5 * 4 * 64) return;
    int which = idx >= 1280;
    int r = which ? idx - 1280 : idx;
    int i = r & 63, lt = r >> 6;
    const float* W = which ? Wd : Ws;
    const float* a = which ? ad : as;
    float* o = which ? wdv : wsv;
    float acc = 0.f;
    const float* wr = W + (size_t)(lt * 64 + i) * 64;
    const float* ar = a + lt * 64;
    #pragma unroll 8
    for (int j = 0; j < 64; j++) acc = fmaf(wr[j], ar[j], acc);
    o[r] = acc;
}

// ---------------- embed ----------------
__global__ void embed_k(const float* __restrict__ mass, const int* __restrict__ pstate,
                        const float* __restrict__ embW, const float* __restrict__ embS,
                        float* __restrict__ xp) {
    int idx = blockIdx.x * blockDim.x + threadIdx.x;
    if (idx >= NPC * 64) return;
    int n = idx >> 6, j = idx & 63;
    float v;
    if (j < 32) v = mass[n] * embW[j];
    else {
        int st = pstate[2 * n] + 2 * pstate[2 * n + 1];
        v = embS[st * 32 + (j - 32)];
    }
    xp[idx] = v;
}

// ---------------- up to 4 per-row dot products (layer-0 init) ----------------
__global__ void dot4(const float* __restrict__ X, int n,
                     const float* v0, float* o0, const float* v1, float* o1,
                     const float* v2, float* o2, const float* v3, float* o3) {
    int idx = blockIdx.x * blockDim.x + threadIdx.x;
    int w = idx >> 5;
    if (w >= n) return;
    int lane = idx & 31;
    float2 x = *(const float2*)&X[(size_t)w * 64 + lane * 2];
#define DODOT(v, o) if (v) { \
        float s = x.x * v[2 * lane] + x.y * v[2 * lane + 1]; \
        for (int off = 16; off; off >>= 1) s += __shfl_xor_sync(FULLMASK, s, off); \
        if (lane == 0) o[w] = s; }
    DODOT(v0, o0)
    DODOT(v1, o1)
    DODOT(v2, o2)
    DODOT(v3, o3)
#undef DODOT
}

// ---------------- bootstrap hs matmul ----------------
__global__ void __launch_bounds__(256) mm_hs(const float* __restrict__ X,
                                             const float* __restrict__ W0, float* __restrict__ Y0,
                                             const float* __restrict__ W1, float* __restrict__ Y1) {
    __shared__ float Xs[64][65];
    __shared__ float Wsh[64][68];
    int half = blockIdx.x >= (NPC / 64);
    int row0 = (half ? blockIdx.x - NPC / 64 : blockIdx.x) * 64;
    const float* W = half ? W1 : W0;
    float* Y = half ? Y1 : Y0;
    int tid = threadIdx.x;
    const float4* W4 = (const float4*)W;
    for (int i = tid; i < 1024; i += 256) {
        float4 v = W4[i];
        int r = i >> 4, c = (i & 15) * 4;
        Wsh[r][c] = v.x; Wsh[r][c + 1] = v.y; Wsh[r][c + 2] = v.z; Wsh[r][c + 3] = v.w;
    }
    const float4* X4 = (const float4*)(X + (size_t)row0 * 64);
    for (int i = tid; i < 1024; i += 256) {
        float4 v = X4[i];
        int r = i >> 4, c = (i & 15) * 4;
        Xs[r][c] = v.x; Xs[r][c + 1] = v.y; Xs[r][c + 2] = v.z; Xs[r][c + 3] = v.w;
    }
    __syncthreads();
    int tx = tid & 15, ty = tid >> 4;
    int c0 = tx * 4, r0 = ty * 4;
    float acc[4][4] = {};
    #pragma unroll
    for (int k = 0; k < 64; k++) {
        float4 w = *(const float4*)&Wsh[k][c0];
        float x0 = Xs[r0][k], x1 = Xs[r0 + 1][k], x2 = Xs[r0 + 2][k], x3 = Xs[r0 + 3][k];
        acc[0][0] = fmaf(x0, w.x, acc[0][0]); acc[0][1] = fmaf(x0, w.y, acc[0][1]);
        acc[0][2] = fmaf(x0, w.z, acc[0][2]); acc[0][3] = fmaf(x0, w.w, acc[0][3]);
        acc[1][0] = fmaf(x1, w.x, acc[1][0]); acc[1][1] = fmaf(x1, w.y, acc[1][1]);
        acc[1][2] = fmaf(x1, w.z, acc[1][2]); acc[1][3] = fmaf(x1, w.w, acc[1][3]);
        acc[2][0] = fmaf(x2, w.x, acc[2][0]); acc[2][1] = fmaf(x2, w.y, acc[2][1]);
        acc[2][2] = fmaf(x2, w.z, acc[2][2]); acc[2][3] = fmaf(x2, w.w, acc[2][3]);
        acc[3][0] = fmaf(x3, w.x, acc[3][0]); acc[3][1] = fmaf(x3, w.y, acc[3][1]);
        acc[3][2] = fmaf(x3, w.z, acc[3][2]); acc[3][3] = fmaf(x3, w.w, acc[3][3]);
    }
    #pragma unroll
    for (int i = 0; i < 4; i++)
        *(float4*)&Y[((size_t)(row0 + r0 + i)) * 64 + c0] =
            make_float4(acc[i][0], acc[i][1], acc[i][2], acc[i][3]);
}

// ================== MEGA (R13 shape): p-dst 64 rows/block 8 lanes/row + t/f agg ==========
__global__ void __launch_bounds__(512, 2) mega(
        int npBlocks, int ntfA,
        const int* rp1, const int* cs1, const float* ss1, const float* sd1,
        const float* X1, const float* W1,
        const int* rp2, const int* cs2, const float* ss2, const float* sd2,
        const float* X2, const float* W2,
        const float* b1, const float* b2, float* Yp, int relu,
        const float* pv0, float* po0, const float* pv1, float* po1,
        const float* pv2, float* po2, const float* pv3, float* po3,
        const float* Wn0, float* hsOut0, const float* Wn1, float* hsOut1,
        const int* rpA, const int* csA, const float* ssA, const float* sdA,
        const float* hsA, const float* bA, float* YA,
        const float* vA0, float* oA0, const float* vA1, float* oA1,
        const int* rpB, const int* csB, const float* ssB, const float* sdB,
        const float* hsB, const float* bB, float* YB,
        const float* vB0, float* oB0, const float* vB1, float* oB1) {
    __shared__ float Zs[64 * 68];
    __shared__ float Wsh[64][68];
    int tid = threadIdx.x;

    if ((int)blockIdx.x < npBlocks) {
        // ---------------- p-part: 64 rows, 8 lanes/row (4 col x 2 edge-subgroups) ----------
        int row0 = blockIdx.x * 64;
        int g8 = tid >> 3, l8 = tid & 7;
        int gl = l8 & 3, sg = l8 >> 2;
        int tx = tid & 15, ty = tid >> 4;
        int c0 = tx * 4, r0 = ty * 2;
        float acc[2][4] = {};
        int d = row0 + g8;
        for (int p = 0; p < 2; p++) {
            const int* rp = p ? rp2 : rp1;
            const int* cs = p ? cs2 : cs1;
            const float* ss = p ? ss2 : ss1;
            const float* sd = p ? sd2 : sd1;
            const float* X = p ? X2 : X1;
            const float* W = p ? W2 : W1;
            const float4* W4 = (const float4*)W;
            for (int i = tid; i < 1024; i += 512) {
                float4 v = W4[i];
                int r = i >> 4, c = (i & 15) * 4;
                Wsh[r][c] = v.x; Wsh[r][c + 1] = v.y; Wsh[r][c + 2] = v.z; Wsh[r][c + 3] = v.w;
            }
            int beg = rp[d], end = rp[d + 1];
            float sdv = sd[d];
            float m = -1e30f;
            for (int j = beg + l8; j < end; j += 8) {
                float t = ss[cs[j]] + sdv;
                t = t > 0.f ? t : 0.2f * t;
                m = fmaxf(m, t);
            }
            m = fmaxf(m, __shfl_xor_sync(FULLMASK, m, 1));
            m = fmaxf(m, __shfl_xor_sync(FULLMASK, m, 2));
            m = fmaxf(m, __shfl_xor_sync(FULLMASK, m, 4));
            float s = 0.f;
            float4 a0 = {0,0,0,0}, a1 = {0,0,0,0}, a2 = {0,0,0,0}, a3 = {0,0,0,0};
            const float4* H4 = (const float4*)X;
            #pragma unroll 2
            for (int j = beg + sg; j < end; j += 2) {
                int src = cs[j];
                float t = ss[src] + sdv;
                t = t > 0.f ? t : 0.2f * t;
                float ex = __expf(t - m);
                s += ex;
                size_t hb = (size_t)src * 16 + gl * 4;
                float4 h0 = H4[hb], h1 = H4[hb + 1], h2 = H4[hb + 2], h3 = H4[hb + 3];
                a0.x = fmaf(ex, h0.x, a0.x); a0.y = fmaf(ex, h0.y, a0.y);
                a0.z = fmaf(ex, h0.z, a0.z); a0.w = fmaf(ex, h0.w, a0.w);
                a1.x = fmaf(ex, h1.x, a1.x); a1.y = fmaf(ex, h1.y, a1.y);
                a1.z = fmaf(ex, h1.z, a1.z); a1.w = fmaf(ex, h1.w, a1.w);
                a2.x = fmaf(ex, h2.x, a2.x); a2.y = fmaf(ex, h2.y, a2.y);
                a2.z = fmaf(ex, h2.z, a2.z); a2.w = fmaf(ex, h2.w, a2.w);
                a3.x = fmaf(ex, h3.x, a3.x); a3.y = fmaf(ex, h3.y, a3.y);
                a3.z = fmaf(ex, h3.z, a3.z); a3.w = fmaf(ex, h3.w, a3.w);
            }
            s += __shfl_xor_sync(FULLMASK, s, 4);
            a0.x += __shfl_xor_sync(FULLMASK, a0.x, 4); a0.y += __shfl_xor_sync(FULLMASK, a0.y, 4);
            a0.z += __shfl_xor_sync(FULLMASK, a0.z, 4); a0.w += __shfl_xor_sync(FULLMASK, a0.w, 4);
            a1.x += __shfl_xor_sync(FULLMASK, a1.x, 4); a1.y += __shfl_xor_sync(FULLMASK, a1.y, 4);
            a1.z += __shfl_xor_sync(FULLMASK, a1.z, 4); a1.w += __shfl_xor_sync(FULLMASK, a1.w, 4);
            a2.x += __shfl_xor_sync(FULLMASK, a2.x, 4); a2.y += __shfl_xor_sync(FULLMASK, a2.y, 4);
            a2.z += __shfl_xor_sync(FULLMASK, a2.z, 4); a2.w += __shfl_xor_sync(FULLMASK, a2.w, 4);
            a3.x += __shfl_xor_sync(FULLMASK, a3.x, 4); a3.y += __shfl_xor_sync(FULLMASK, a3.y, 4);
            a3.z += __shfl_xor_sync(FULLMASK, a3.z, 4); a3.w += __shfl_xor_sync(FULLMASK, a3.w, 4);
            float inv = s > 0.f ? 1.f / s : 0.f;
            if (sg == 0) {
                float4* Zr = (float4*)&Zs[g8 * 68];
                Zr[gl * 4]     = make_float4(a0.x * inv, a0.y * inv, a0.z * inv, a0.w * inv);
                Zr[gl * 4 + 1] = make_float4(a1.x * inv, a1.y * inv, a1.z * inv, a1.w * inv);
                Zr[gl * 4 + 2] = make_float4(a2.x * inv, a2.y * inv, a2.z * inv, a2.w * inv);
                Zr[gl * 4 + 3] = make_float4(a3.x * inv, a3.y * inv, a3.z * inv, a3.w * inv);
            }
            __syncthreads();
            #pragma unroll
            for (int k = 0; k < 64; k++) {
                float4 wv = *(const float4*)&Wsh[k][c0];
                float x0 = Zs[r0 * 68 + k], x1 = Zs[(r0 + 1) * 68 + k];
                acc[0][0] = fmaf(x0, wv.x, acc[0][0]); acc[0][1] = fmaf(x0, wv.y, acc[0][1]);
                acc[0][2] = fmaf(x0, wv.z, acc[0][2]); acc[0][3] = fmaf(x0, wv.w, acc[0][3]);
                acc[1][0] = fmaf(x1, wv.x, acc[1][0]); acc[1][1] = fmaf(x1, wv.y, acc[1][1]);
                acc[1][2] = fmaf(x1, wv.z, acc[1][2]); acc[1][3] = fmaf(x1, wv.w, acc[1][3]);
            }
            __syncthreads();
        }
        #pragma unroll
        for (int i = 0; i < 2; i++)
            #pragma unroll
            for (int c = 0; c < 4; c++) {
                float v = acc[i][c] + b1[c0 + c] + b2[c0 + c];
                if (relu) v = fmaxf(v, 0.f);
                Zs[(r0 + i) * 68 + c0 + c] = v;
            }
        __syncthreads();
        float4 ot[2];
        const float4* Zr = (const float4*)&Zs[g8 * 68];
        ot[0] = Zr[l8 * 2]; ot[1] = Zr[l8 * 2 + 1];
        float4* Yr = (float4*)&Yp[(size_t)d * 64];
        Yr[l8 * 2] = ot[0]; Yr[l8 * 2 + 1] = ot[1];
#define PDOT(v, o) if (v) { \
        const float4* V4 = (const float4*)v; \
        float4 vv0 = V4[l8 * 2], vv1 = V4[l8 * 2 + 1]; \
        float dd = ot[0].x * vv0.x + ot[0].y * vv0.y + ot[0].z * vv0.z + ot[0].w * vv0.w \
                 + ot[1].x * vv1.x + ot[1].y * vv1.y + ot[1].z * vv1.z + ot[1].w * vv1.w; \
        dd += __shfl_xor_sync(FULLMASK, dd, 1); \
        dd += __shfl_xor_sync(FULLMASK, dd, 2); \
        dd += __shfl_xor_sync(FULLMASK, dd, 4); \
        if (l8 == 0) o[d] = dd; }
        PDOT(pv0, po0)
        PDOT(pv1, po1)
        PDOT(pv2, po2)
        PDOT(pv3, po3)
#undef PDOT
        // ---- hs epilogue ----
        if (Wn0) {
            for (int p = 0; p < 2; p++) {
                const float* Wn = p ? Wn1 : Wn0;
                float* hsO = p ? hsOut1 : hsOut0;
                const float4* Wn4 = (const float4*)Wn;
                __syncthreads();
                for (int i = tid; i < 1024; i += 512) {
                    float4 v = Wn4[i];
                    int r = i >> 4, c = (i & 15) * 4;
                    Wsh[r][c] = v.x; Wsh[r][c + 1] = v.y; Wsh[r][c + 2] = v.z; Wsh[r][c + 3] = v.w;
                }
                __syncthreads();
                float ea[2][4] = {};
                #pragma unroll
                for (int k = 0; k < 64; k++) {
                    float4 wv = *(const float4*)&Wsh[k][c0];
                    float x0 = Zs[r0 * 68 + k], x1 = Zs[(r0 + 1) * 68 + k];
                    ea[0][0] = fmaf(x0, wv.x, ea[0][0]); ea[0][1] = fmaf(x0, wv.y, ea[0][1]);
                    ea[0][2] = fmaf(x0, wv.z, ea[0][2]); ea[0][3] = fmaf(x0, wv.w, ea[0][3]);
                    ea[1][0] = fmaf(x1, wv.x, ea[1][0]); ea[1][1] = fmaf(x1, wv.y, ea[1][1]);
                    ea[1][2] = fmaf(x1, wv.z, ea[1][2]); ea[1][3] = fmaf(x1, wv.w, ea[1][3]);
                }
                #pragma unroll
                for (int i = 0; i < 2; i++)
                    *(float4*)&hsO[((size_t)(row0 + r0 + i)) * 64 + c0] =
                        make_float4(ea[i][0], ea[i][1], ea[i][2], ea[i][3]);
            }
        }
    } else {
        // ---------------- tf-part: 4 lanes/row, two-pass fixed-max ----------------
        int tfIdx = blockIdx.x - npBlocks;
        bool isA = tfIdx < ntfA;
        int row0 = (isA ? tfIdx : tfIdx - ntfA) * 128;
        const int* rp = isA ? rpA : rpB;
        const int* cs = isA ? csA : csB;
        const float* ss = isA ? ssA : ssB;
        const float* sd = isA ? sdA : sdB;
        const float* hs = isA ? hsA : hsB;
        const float* b = isA ? bA : bB;
        float* Y = isA ? YA : YB;
        const float* v0 = isA ? vA0 : vB0;  float* o0 = isA ? oA0 : oB0;
        const float* v1 = isA ? vA1 : vB1;  float* o1 = isA ? oA1 : oB1;

        int g = tid >> 2, gl = tid & 3;
        int d = row0 + g;
        int beg = rp[d], end = rp[d + 1];
        float sdv = sd[d];
        float m = -1e30f;
        for (int j = beg + gl; j < end; j += 4) {
            float t = ss[cs[j]] + sdv;
            t = t > 0.f ? t : 0.2f * t;
            m = fmaxf(m, t);
        }
        m = fmaxf(m, __shfl_xor_sync(FULLMASK, m, 1));
        m = fmaxf(m, __shfl_xor_sync(FULLMASK, m, 2));
        float s = 0.f;
        float4 a0 = {0,0,0,0}, a1 = {0,0,0,0}, a2 = {0,0,0,0}, a3 = {0,0,0,0};
        const float4* H4 = (const float4*)hs;
        #pragma unroll 2
        for (int j = beg; j < end; j++) {
            int src = cs[j];
            float t = ss[src] + sdv;
            t = t > 0.f ? t : 0.2f * t;
            float ex = __expf(t - m);
            s += ex;
            size_t hb = (size_t)src * 16 + gl * 4;
            float4 h0 = H4[hb], h1 = H4[hb + 1], h2 = H4[hb + 2], h3 = H4[hb + 3];
            a0.x = fmaf(ex, h0.x, a0.x); a0.y = fmaf(ex, h0.y, a0.y);
            a0.z = fmaf(ex, h0.z, a0.z); a0.w = fmaf(ex, h0.w, a0.w);
            a1.x = fmaf(ex, h1.x, a1.x); a1.y = fmaf(ex, h1.y, a1.y);
            a1.z = fmaf(ex, h1.z, a1.z); a1.w = fmaf(ex, h1.w, a1.w);
            a2.x = fmaf(ex, h2.x, a2.x); a2.y = fmaf(ex, h2.y, a2.y);
            a2.z = fmaf(ex, h2.z, a2.z); a2.w = fmaf(ex, h2.w, a2.w);
            a3.x = fmaf(ex, h3.x, a3.x); a3.y = fmaf(ex, h3.y, a3.y);
            a3.z = fmaf(ex, h3.z, a3.z); a3.w = fmaf(ex, h3.w, a3.w);
        }
        float inv = s > 0.f ? 1.f / s : 0.f;
        const float4* B4 = (const float4*)b;
        float4 bb0 = B4[gl * 4], bb1 = B4[gl * 4 + 1], bb2 = B4[gl * 4 + 2], bb3 = B4[gl * 4 + 3];
        float4 ot[4];
        ot[0] = make_float4(a0.x * inv + bb0.x, a0.y * inv + bb0.y, a0.z * inv + bb0.z, a0.w * inv + bb0.w);
        ot[1] = make_float4(a1.x * inv + bb1.x, a1.y * inv + bb1.y, a1.z * inv + bb1.z, a1.w * inv + bb1.w);
        ot[2] = make_float4(a2.x * inv + bb2.x, a2.y * inv + bb2.y, a2.z * inv + bb2.z, a2.w * inv + bb2.w);
        ot[3] = make_float4(a3.x * inv + bb3.x, a3.y * inv + bb3.y, a3.z * inv + bb3.z, a3.w * inv + bb3.w);
        if (relu) {
            #pragma unroll
            for (int q = 0; q < 4; q++) {
                ot[q].x = fmaxf(ot[q].x, 0.f); ot[q].y = fmaxf(ot[q].y, 0.f);
                ot[q].z = fmaxf(ot[q].z, 0.f); ot[q].w = fmaxf(ot[q].w, 0.f);
            }
        }
        float4* Yr = (float4*)&Y[(size_t)d * 64];
        #pragma unroll
        for (int q = 0; q < 4; q++) Yr[gl * 4 + q] = ot[q];
#define TDOT(v, o) { \
        const float4* V4 = (const float4*)v; \
        float dd = 0.f; \
        _Pragma("unroll") \
        for (int q = 0; q < 4; q++) { \
            float4 vv = V4[gl * 4 + q]; \
            dd += ot[q].x * vv.x + ot[q].y * vv.y + ot[q].z * vv.z + ot[q].w * vv.w; \
        } \
        dd += __shfl_xor_sync(FULLMASK, dd, 1); \
        dd += __shfl_xor_sync(FULLMASK, dd, 2); \
        if (gl == 0) o[d] = dd; }
        TDOT(v0, o0)
        TDOT(v1, o1)
#undef TDOT
    }
}

// ---------------- fused pooling: 3 tables in one launch ----------------
__global__ void pool3(const float* __restrict__ xp, const float* __restrict__ xt,
                      const float* __restrict__ xf, float* __restrict__ rep) {
    int which = blockIdx.y;
    const float* x = (which == 0) ? xp : (which == 1) ? xt : xf;
    int npg = (which == 0) ? 64 : 512;
    int off = which * 192;
    int b = blockIdx.x;
    int t = threadIdx.x;            // 256
    int d = t & 63, c = t >> 6;
    const float* base = x + (size_t)b * npg * 64;
    float mx = -1e30f, mn = 1e30f, sm = 0.f;
    for (int n = c; n < npg; n += 4) {
        float v = base[(size_t)n * 64 + d];
        mx = fmaxf(mx, v); mn = fminf(mn, v); sm += v;
    }
    __shared__ float smx[4][64], smn[4][64], ssm[4][64];
    smx[c][d] = mx; smn[c][d] = mn; ssm[c][d] = sm;
    __syncthreads();
    if (c == 0) {
        for (int i = 1; i < 4; i++) {
            mx = fmaxf(mx, smx[i][d]); mn = fminf(mn, smn[i][d]); sm += ssm[i][d];
        }
        rep[b * 576 + off + d] = mx;
        rep[b * 576 + off + 64 + d] = mn;
        rep[b * 576 + off + 128 + d] = sm / (float)npg;
    }
}

// ---------------- fused actor head: LayerNorm + out_a + per-graph softmax + scatter -------
// one block per graph, 64 threads (one per node)
__global__ void actor_head(const float* __restrict__ ap, const float* __restrict__ g,
                           const float* __restrict__ be, const float* __restrict__ Wa,
                           const float* __restrict__ ba, const int* __restrict__ part_id,
                           float* __restrict__ out) {
    __shared__ float sh[2];
    __shared__ float wa_s[128], g_s[64], be_s[64];
    int b = blockIdx.x, t = threadIdx.x;      // 64
    if (t < 64) {
        g_s[t] = g[t]; be_s[t] = be[t];
        wa_s[2 * t] = Wa[2 * t]; wa_s[2 * t + 1] = Wa[2 * t + 1];
    }
    __syncthreads();
    int n = b * 64 + t;
    // LayerNorm over the node's 64 dims (serial in-thread; rows are L2-resident)
    const float4* A4 = (const float4*)&ap[(size_t)n * 64];
    float4 va[16];
    float sum = 0.f;
    #pragma unroll
    for (int q = 0; q < 16; q++) { va[q] = A4[q]; sum += va[q].x + va[q].y + va[q].z + va[q].w; }
    float mu = sum * (1.f / 64.f);
    float vs = 0.f;
    #pragma unroll
    for (int q = 0; q < 16; q++) {
        float dx = va[q].x - mu, dy = va[q].y - mu, dz = va[q].z - mu, dw = va[q].w - mu;
        vs += dx * dx + dy * dy + dz * dz + dw * dw;
    }
    float rs = rsqrtf(vs * (1.f / 64.f) + 1e-5f);
    float r0 = 0.f, r1 = 0.f;
    #pragma unroll
    for (int q = 0; q < 16; q++) {
        float y0 = (va[q].x - mu) * rs * g_s[4 * q]     + be_s[4 * q];
        float y1 = (va[q].y - mu) * rs * g_s[4 * q + 1] + be_s[4 * q + 1];
        float y2 = (va[q].z - mu) * rs * g_s[4 * q + 2] + be_s[4 * q + 2];
        float y3 = (va[q].w - mu) * rs * g_s[4 * q + 3] + be_s[4 * q + 3];
        r0 += y0 * wa_s[(4 * q) * 2] + y1 * wa_s[(4 * q + 1) * 2]
            + y2 * wa_s[(4 * q + 2) * 2] + y3 * wa_s[(4 * q + 3) * 2];
        r1 += y0 * wa_s[(4 * q) * 2 + 1] + y1 * wa_s[(4 * q + 1) * 2 + 1]
            + y2 * wa_s[(4 * q + 2) * 2 + 1] + y3 * wa_s[(4 * q + 3) * 2 + 1];
    }
    r0 += ba[0]; r1 += ba[1];
    // per-graph softmax over the 64 nodes (block = graph)
    float v = r0;
    for (int o = 16; o; o >>= 1) v = fmaxf(v, __shfl_xor_sync(FULLMASK, v, o));
    if ((t & 31) == 0) sh[t >> 5] = v;
    __syncthreads();
    float m0 = fmaxf(sh[0], sh[1]);
    __syncthreads();
    v = r1;
    for (int o = 16; o; o >>= 1) v = fmaxf(v, __shfl_xor_sync(FULLMASK, v, o));
    if ((t & 31) == 0) sh[t >> 5] = v;
    __syncthreads();
    float m1 = fmaxf(sh[0], sh[1]);
    __syncthreads();
    float e0 = expf(r0 - m0), e1 = expf(r1 - m1);
    v = e0;
    for (int o = 16; o; o >>= 1) v += __shfl_xor_sync(FULLMASK, v, o);
    if ((t & 31) == 0) sh[t >> 5] = v;
    __syncthreads();
    float s0 = sh[0] + sh[1];
    __syncthreads();
    v = e1;
    for (int o = 16; o; o >>= 1) v += __shfl_xor_sync(FULLMASK, v, o);
    if ((t & 31) == 0) sh[t >> 5] = v;
    __syncthreads();
    float s1 = sh[0] + sh[1];
    int p = part_id[n];
    out[b * 128 + p] = e0 / s0;
    out[b * 128 + 64 + p] = e1 / s1;
}

// ---------------- fused value head: gelu(rep@W1+b1) -> gelu(@W2+b2) -> tanh(@Wo+bo) ------
__global__ void vhead(const float* __restrict__ rep,
                      const float* __restrict__ W1, const float* __restrict__ b1,
                      const float* __restrict__ W2, const float* __restrict__ b2,
                      const float* __restrict__ Wo, const float* __restrict__ bo,
                      float* __restrict__ V) {
    __shared__ float s[576];
    __shared__ float h[64];
    __shared__ float sh[2];
    int b = blockIdx.x, j = threadIdx.x;      // 64
    for (int k = j; k < 576; k += 64) s[k] = rep[b * 576 + k];
    __syncthreads();
    float acc = b1[j];
    for (int k = 0; k < 576; k++) acc = fmaf(s[k], W1[k * 64 + j], acc);
    acc = 0.5f * acc * (1.f + erff(acc * 0.70710678118654752f));
    h[j] = acc;
    __syncthreads();
    float acc2 = b2[j];
    #pragma unroll 8
    for (int k = 0; k < 64; k++) acc2 = fmaf(h[k], W2[k * 64 + j], acc2);
    acc2 = 0.5f * acc2 * (1.f + erff(acc2 * 0.70710678118654752f));
    // dot with Wo across 64 threads
    float part = acc2 * Wo[j];
    for (int o = 16; o; o >>= 1) part += __shfl_xor_sync(FULLMASK, part, o);
    if ((j & 31) == 0) sh[j >> 5] = part;
    __syncthreads();
    if (j == 0) V[b] = tanhf(sh[0] + sh[1] + bo[0]);
}

// ---------------- host ----------------
#define SYMF(p, s) do { void* _q; cudaGetSymbolAddress(&_q, s); p = (float*)_q; } while (0)
#define SYMI(p, s) do { void* _q; cudaGetSymbolAddress(&_q, s); p = (int*)_q; } while (0)

extern "C" void kernel_launch(void* const* d_in, const int* in_sizes, int n_in,
                              void* d_out, int out_size) {
    const float* mass      = (const float*)d_in[0];
    const int*   pstate    = (const int*)d_in[1];
    const float* torque_x  = (const float*)d_in[2];
    const float* force_x   = (const float*)d_in[3];
    const int* e_pt_src = (const int*)d_in[4];
    const int* e_pt_dst = (const int*)d_in[5];
    const int* e_tp_src = (const int*)d_in[6];
    const int* e_tp_dst = (const int*)d_in[7];
    const int* e_pf_src = (const int*)d_in[8];
    const int* e_pf_dst = (const int*)d_in[9];
    const int* e_fp_src = (const int*)d_in[10];
    const int* e_fp_dst = (const int*)d_in[11];
    const int* part_id  = (const int*)d_in[13];
    const float* embW   = (const float*)d_in[14];
    const float* embS   = (const float*)d_in[15];
    const float* W_src  = (const float*)d_in[16];
    const float* W_dst  = (const float*)d_in[17];
    const float* a_src  = (const float*)d_in[18];
    const float* a_dst  = (const float*)d_in[19];
    const float* b_conv = (const float*)d_in[20];
    const float* ln_g   = (const float*)d_in[21];
    const float* ln_b   = (const float*)d_in[22];
    const float* outaW  = (const float*)d_in[23];
    const float* outab  = (const float*)d_in[24];
    const float* innW   = (const float*)d_in[25];
    const float* innb   = (const float*)d_in[26];
    const float* fulW   = (const float*)d_in[27];
    const float* fulb   = (const float*)d_in[28];
    const float* outW   = (const float*)d_in[29];
    const float* outb   = (const float*)d_in[30];
    float* out = (float*)d_out;

    float *xp, *xt, *xf, *ap, *hs0, *hs1;
    float *ss_pt, *ss_pf, *sd_tp, *sd_fp, *ss_tp, *sd_pt, *ss_fp, *sd_pf;
    float *wsv, *wdv, *rep;
    int *rp_pt, *rp_pf, *rp_tp, *rp_fp, *cs_pt, *cs_tp, *cs_pf, *cs_fp, *cnt, *aux;
    SYMF(xp, g_xp); SYMF(xt, g_xt); SYMF(xf, g_xf); SYMF(ap, g_ap);
    SYMF(hs0, g_hs0); SYMF(hs1, g_hs1);
    SYMF(ss_pt, g_ss_pt); SYMF(ss_pf, g_ss_pf); SYMF(sd_tp, g_sd_tp); SYMF(sd_fp, g_sd_fp);
    SYMF(ss_tp, g_ss_tp); SYMF(sd_pt, g_sd_pt); SYMF(ss_fp, g_ss_fp); SYMF(sd_pf, g_sd_pf);
    SYMF(wsv, g_wsv); SYMF(wdv, g_wdv); SYMF(rep, g_rep);
    SYMI(rp_pt, g_rp_pt); SYMI(rp_pf, g_rp_pf); SYMI(rp_tp, g_rp_tp); SYMI(rp_fp, g_rp_fp);
    SYMI(cs_pt, g_cs_pt); SYMI(cs_tp, g_cs_tp); SYMI(cs_pf, g_cs_pf); SYMI(cs_fp, g_cs_fp);
    SYMI(cnt, g_cnt); SYMI(aux, g_aux);

    // batched CSR build (parallel 3-phase scan)
    zero4<<<(4 * NTC) / 256, 256>>>(cnt);
    { dim3 g(EC / 256, 4); hist4<<<g, 256>>>(e_pt_dst, e_tp_dst, e_pf_dst, e_fp_dst, cnt); }
    { dim3 g(128, 4); scanA<<<g, 1024>>>(cnt, rp_pt, rp_tp, rp_pf, rp_fp, aux); }
    scanB<<<1, 512>>>(aux);
    { dim3 g(128, 4); scanC<<<g, 1024>>>(cnt, rp_pt, rp_tp, rp_pf, rp_fp, aux); }
    { dim3 g(EC / 256, 4);
      scatter4<<<g, 256>>>(e_pt_src, e_pt_dst, e_tp_src, e_tp_dst,
                           e_pf_src, e_pf_dst, e_fp_src, e_fp_dst,
                           rp_pt, rp_tp, rp_pf, rp_fp, cnt,
                           cs_pt, cs_tp, cs_pf, cs_fp); }

    // score vectors; embed; layer-0 score dots; bootstrap hs (parity 0)
    vec_all<<<10, 256>>>(W_src, a_src, W_dst, a_dst, wsv, wdv);
    dot4<<<(NTC * 32) / 256, 256>>>(torque_x, NTC,
         wsv + 1 * 64, ss_tp, wdv + 0 * 64, sd_pt, nullptr, nullptr, nullptr, nullptr);
    dot4<<<(NFC * 32) / 256, 256>>>(force_x, NFC,
         wsv + 3 * 64, ss_fp, wdv + 2 * 64, sd_pf, nullptr, nullptr, nullptr, nullptr);
    embed_k<<<(NPC * 64) / 256, 256>>>(mass, pstate, embW, embS, xp);
    dot4<<<(NPC * 32) / 256, 256>>>(xp, NPC,
         wsv + 0 * 64, ss_pt, wsv + 2 * 64, ss_pf,
         wdv + 1 * 64, sd_tp, wdv + 3 * 64, sd_fp);
    mm_hs<<<2 * (NPC / 64), 256>>>(xp, W_src + 0 * 4096, hs0, W_src + 2 * 4096, hs1);

    for (int l = 0; l < 5; l++) {
        int ci = l & 1, ni = (l + 1) & 1;
        const float* xti = (l == 0) ? torque_x : xt + (size_t)ni * NTC * 64;
        const float* xfi = (l == 0) ? force_x  : xf + (size_t)ni * NFC * 64;
        float* xto = xt + (size_t)ci * NTC * 64;
        float* xfo = xf + (size_t)ci * NFC * 64;
        const float* Wl = W_src + (size_t)l * 4 * 4096;
        const float* bl = b_conv + (size_t)l * 4 * 64;
        int relu = (l < 3) ? 1 : 0;
        int actor = (l == 4);
        const float* nwsv = wsv + (size_t)(l + 1) * 4 * 64;
        const float* nwdv = wdv + (size_t)(l + 1) * 4 * 64;
        const float* c_ss_pt = ss_pt + ci * NPC;  float* n_ss_pt = ss_pt + ni * NPC;
        const float* c_ss_pf = ss_pf + ci * NPC;  float* n_ss_pf = ss_pf + ni * NPC;
        const float* c_sd_tp = sd_tp + ci * NPC;  float* n_sd_tp = sd_tp + ni * NPC;
        const float* c_sd_fp = sd_fp + ci * NPC;  float* n_sd_fp = sd_fp + ni * NPC;
        const float* c_ss_tp = ss_tp + ci * NTC;  float* n_ss_tp = ss_tp + ni * NTC;
        const float* c_sd_pt = sd_pt + ci * NTC;  float* n_sd_pt = sd_pt + ni * NTC;
        const float* c_ss_fp = ss_fp + ci * NFC;  float* n_ss_fp = ss_fp + ni * NFC;
        const float* c_sd_pf = sd_pf + ci * NFC;  float* n_sd_pf = sd_pf + ni * NFC;
        const float* hs0c = hs0 + (size_t)ci * NPC * 64;
        const float* hs1c = hs1 + (size_t)ci * NPC * 64;
        float* hs0n = hs0 + (size_t)ni * NPC * 64;
        float* hs1n = hs1 + (size_t)ni * NPC * 64;
        const float* Wnext = W_src + (size_t)(l + 1) * 4 * 4096;
        int doEpi = (l < 3);

        if (!actor) {
            mega<<<NPC / 64 + NTC / 128 + NFC / 128, 512>>>(
                NPC / 64, NTC / 128,
                rp_tp, cs_tp, c_ss_tp, c_sd_tp, xti, Wl + 1 * 4096,
                rp_fp, cs_fp, c_ss_fp, c_sd_fp, xfi, Wl + 3 * 4096,
                bl + 1 * 64, bl + 3 * 64, xp, relu,
                nwsv + 0 * 64, n_ss_pt, nwsv + 2 * 64, n_ss_pf,
                nwdv + 1 * 64, n_sd_tp, nwdv + 3 * 64, n_sd_fp,
                doEpi ? (Wnext + 0 * 4096) : nullptr, hs0n,
                doEpi ? (Wnext + 2 * 4096) : nullptr, hs1n,
                rp_pt, cs_pt, c_ss_pt, c_sd_pt, hs0c, bl + 0 * 64, xto,
                nwsv + 1 * 64, n_ss_tp, nwdv + 0 * 64, n_sd_pt,
                rp_pf, cs_pf, c_ss_pf, c_sd_pf, hs1c, bl + 2 * 64, xfo,
                nwsv + 3 * 64, n_ss_fp, nwdv + 2 * 64, n_sd_pf);
        } else {
            mega<<<NPC / 64, 512>>>(
                NPC / 64, 0,
                rp_tp, cs_tp, c_ss_tp, c_sd_tp, xti, Wl + 1 * 4096,
                rp_fp, cs_fp, c_ss_fp, c_sd_fp, xfi, Wl + 3 * 4096,
                bl + 1 * 64, bl + 3 * 64, ap, 0,
                nullptr, nullptr, nullptr, nullptr,
                nullptr, nullptr, nullptr, nullptr,
                nullptr, nullptr, nullptr, nullptr,
                nullptr, nullptr, nullptr, nullptr, nullptr, nullptr, nullptr,
                nullptr, nullptr, nullptr, nullptr,
                nullptr, nullptr, nullptr, nullptr, nullptr, nullptr, nullptr,
                nullptr, nullptr, nullptr, nullptr);
        }
    }

    // fused pooling: l=3 wrote xt/xf parity 1; xp in place
    { dim3 g(BC, 3); pool3<<<g, 256>>>(xp, xt + (size_t)NTC * 64, xf + (size_t)NFC * 64, rep); }

    // fused heads
    actor_head<<<BC, 64>>>(ap, ln_g, ln_b, outaW, outab, part_id, out);
    vhead<<<BC, 64>>>(rep, innW, innb, fulW, fulb, outW, outb, out + BC * 128);
}

// round 16
// speedup vs baseline: 1.1966x; 1.0320x over previous
#include <cuda_runtime.h>
#include <math.h>

#define NPC 16384
#define NTC 131072
#define NFC 131072
#define EC  262144
#define BC  256
#define FULLMASK 0xffffffffu

// ---------------- device scratch ----------------
__device__ float g_xp[NPC * 64];
__device__ float g_xt[2][NTC * 64];
__device__ float g_xf[2][NFC * 64];
__device__ float g_ap[NPC * 64];
__device__ float g_hs0[2][NPC * 64];
__device__ float g_hs1[2][NPC * 64];
__device__ float g_ss_pt[2][NPC], g_ss_pf[2][NPC], g_sd_tp[2][NPC], g_sd_fp[2][NPC];
__device__ float g_ss_tp[2][NTC], g_sd_pt[2][NTC];
__device__ float g_ss_fp[2][NFC], g_sd_pf[2][NFC];
__device__ float g_wsv[5 * 4 * 64], g_wdv[5 * 4 * 64];
__device__ int g_rp_pt[NTC + 1], g_rp_pf[NFC + 1];
__device__ int g_rp_tp[NPC + 1], g_rp_fp[NPC + 1];
__device__ int g_cs_pt[EC], g_cs_tp[EC], g_cs_pf[EC], g_cs_fp[EC];
__device__ int g_cnt[4 * NTC];
__device__ int g_aux[520];
__device__ float g_rep[BC * 576];

// ---------------- batched CSR build ----------------
__global__ void zero4(int* c) {
    int i = blockIdx.x * blockDim.x + threadIdx.x;
    if (i < 4 * NTC) c[i] = 0;
}

__global__ void hist4(const int* __restrict__ d0, const int* __restrict__ d1,
                      const int* __restrict__ d2, const int* __restrict__ d3,
                      int* __restrict__ cnt) {
    int t = blockIdx.y;
    const int* d = (t == 0) ? d0 : (t == 1) ? d1 : (t == 2) ? d2 : d3;
    int* c = cnt + t * NTC;
    int i = blockIdx.x * blockDim.x + threadIdx.x;
    if (i < EC) atomicAdd(&c[d[i]], 1);
}

__global__ void __launch_bounds__(1024) scanA(const int* __restrict__ cnt,
        int* rp0, int* rp1, int* rp2, int* rp3, int* __restrict__ aux) {
    __shared__ int ws[32];
    int t = blockIdx.y;
    int* rowptr = (t == 0) ? rp0 : (t == 1) ? rp1 : (t == 2) ? rp2 : rp3;
    int n = (t == 0) ? NTC : (t == 1) ? NPC : (t == 2) ? NFC : NPC;
    const int* deg = cnt + t * NTC;
    int tid = threadIdx.x, lane = tid & 31, wid = tid >> 5;
    int i = blockIdx.x * 1024 + tid;
    int v = (i < n) ? deg[i] : 0;
    int x = v;
    #pragma unroll
    for (int off = 1; off < 32; off <<= 1) {
        int y = __shfl_up_sync(FULLMASK, x, off);
        if (lane >= off) x += y;
    }
    if (lane == 31) ws[wid] = x;
    __syncthreads();
    if (tid < 32) {
        int s = ws[tid];
        #pragma unroll
        for (int off = 1; off < 32; off <<= 1) {
            int y = __shfl_up_sync(FULLMASK, s, off);
            if (tid >= off) s += y;
        }
        ws[tid] = s;
    }
    __syncthreads();
    int excl = x - v + (wid ? ws[wid - 1] : 0);
    if (i < n) rowptr[i] = excl;
    if (tid == 0) aux[t * 128 + blockIdx.x] = ws[31];
}

__global__ void __launch_bounds__(512) scanB(int* __restrict__ aux) {
    __shared__ int wsum[16];
    int tid = threadIdx.x;
    int t = tid >> 7, idx = tid & 127;
    int lane = tid & 31, wid = tid >> 5;
    int v = aux[t * 128 + idx];
    int x = v;
    #pragma unroll
    for (int off = 1; off < 32; off <<= 1) {
        int y = __shfl_up_sync(FULLMASK, x, off);
        if (lane >= off) x += y;
    }
    if (lane == 31) wsum[wid] = x;
    __syncthreads();
    int offsum = 0;
    for (int w = t * 4; w < wid; w++) offsum += wsum[w];
    int excl = x - v + offsum;
    aux[t * 128 + idx] = excl;
    if (idx == 127) aux[512 + t] = excl + v;
}

__global__ void __launch_bounds__(1024) scanC(int* __restrict__ cnt,
        int* rp0, int* rp1, int* rp2, int* rp3, const int* __restrict__ aux) {
    int t = blockIdx.y;
    int* rowptr = (t == 0) ? rp0 : (t == 1) ? rp1 : (t == 2) ? rp2 : rp3;
    int n = (t == 0) ? NTC : (t == 1) ? NPC : (t == 2) ? NFC : NPC;
    int i = blockIdx.x * 1024 + threadIdx.x;
    if (i < n) {
        rowptr[i] += aux[t * 128 + blockIdx.x];
        cnt[t * NTC + i] = 0;
    }
    if (i == 0) rowptr[n] = aux[512 + t];
}

__global__ void scatter4(const int* __restrict__ s0, const int* __restrict__ d0,
                         const int* __restrict__ s1, const int* __restrict__ d1,
                         const int* __restrict__ s2, const int* __restrict__ d2,
                         const int* __restrict__ s3, const int* __restrict__ d3,
                         const int* rp0, const int* rp1, const int* rp2, const int* rp3,
                         int* __restrict__ cnt,
                         int* c0, int* c1, int* c2, int* c3) {
    int t = blockIdx.y;
    const int* src = (t == 0) ? s0 : (t == 1) ? s1 : (t == 2) ? s2 : s3;
    const int* dst = (t == 0) ? d0 : (t == 1) ? d1 : (t == 2) ? d2 : d3;
    const int* rp  = (t == 0) ? rp0 : (t == 1) ? rp1 : (t == 2) ? rp2 : rp3;
    int* csr = (t == 0) ? c0 : (t == 1) ? c1 : (t == 2) ? c2 : c3;
    int* cur = cnt + t * NTC;
    int i = blockIdx.x * blockDim.x + threadIdx.x;
    if (i >= EC) return;
    int d = dst[i];
    int pos = rp[d] + atomicAdd(&cur[d], 1);
    csr[pos] = src[i];
}

// ---------------- score vectors for ALL layers ----------------
__global__ void vec_all(const float* __restrict__ Ws, const float* __restrict__ as,
                        const float* __restrict__ Wd, const float* __restrict__ ad,
                        float* __restrict__ wsv, float* __restrict__ wdv) {
    int idx = blockIdx.x * blockDim.x + threadIdx.x;
    if (idx >= 2 * 5 * 4 * 64) return;
    int which = idx >= 1280;
    int r = which ? idx - 1280 : idx;
    int i = r & 63, lt = r >> 6;
    const float* W = which ? Wd : Ws;
    const float* a = which ? ad : as;
    float* o = which ? wdv : wsv;
    float acc = 0.f;
    const float* wr = W + (size_t)(lt * 64 + i) * 64;
    const float* ar = a + lt * 64;
    #pragma unroll 8
    for (int j = 0; j < 64; j++) acc = fmaf(wr[j], ar[j], acc);
    o[r] = acc;
}

// ---------------- embed ----------------
__global__ void embed_k(const float* __restrict__ mass, const int* __restrict__ pstate,
                        const float* __restrict__ embW, const float* __restrict__ embS,
                        float* __restrict__ xp) {
    int idx = blockIdx.x * blockDim.x + threadIdx.x;
    if (idx >= NPC * 64) return;
    int n = idx >> 6, j = idx & 63;
    float v;
    if (j < 32) v = mass[n] * embW[j];
    else {
        int st = pstate[2 * n] + 2 * pstate[2 * n + 1];
        v = embS[st * 32 + (j - 32)];
    }
    xp[idx] = v;
}

// ---------------- up to 4 per-row dot products (layer-0 init) ----------------
__global__ void dot4(const float* __restrict__ X, int n,
                     const float* v0, float* o0, const float* v1, float* o1,
                     const float* v2, float* o2, const float* v3, float* o3) {
    int idx = blockIdx.x * blockDim.x + threadIdx.x;
    int w = idx >> 5;
    if (w >= n) return;
    int lane = idx & 31;
    float2 x = *(const float2*)&X[(size_t)w * 64 + lane * 2];
#define DODOT(v, o) if (v) { \
        float s = x.x * v[2 * lane] + x.y * v[2 * lane + 1]; \
        for (int off = 16; off; off >>= 1) s += __shfl_xor_sync(FULLMASK, s, off); \
        if (lane == 0) o[w] = s; }
    DODOT(v0, o0)
    DODOT(v1, o1)
    DODOT(v2, o2)
    DODOT(v3, o3)
#undef DODOT
}

// ---------------- bootstrap hs matmul ----------------
__global__ void __launch_bounds__(256) mm_hs(const float* __restrict__ X,
                                             const float* __restrict__ W0, float* __restrict__ Y0,
                                             const float* __restrict__ W1, float* __restrict__ Y1) {
    __shared__ float Xs[64][65];
    __shared__ float Wsh[64][68];
    int half = blockIdx.x >= (NPC / 64);
    int row0 = (half ? blockIdx.x - NPC / 64 : blockIdx.x) * 64;
    const float* W = half ? W1 : W0;
    float* Y = half ? Y1 : Y0;
    int tid = threadIdx.x;
    const float4* W4 = (const float4*)W;
    for (int i = tid; i < 1024; i += 256) {
        float4 v = W4[i];
        int r = i >> 4, c = (i & 15) * 4;
        Wsh[r][c] = v.x; Wsh[r][c + 1] = v.y; Wsh[r][c + 2] = v.z; Wsh[r][c + 3] = v.w;
    }
    const float4* X4 = (const float4*)(X + (size_t)row0 * 64);
    for (int i = tid; i < 1024; i += 256) {
        float4 v = X4[i];
        int r = i >> 4, c = (i & 15) * 4;
        Xs[r][c] = v.x; Xs[r][c + 1] = v.y; Xs[r][c + 2] = v.z; Xs[r][c + 3] = v.w;
    }
    __syncthreads();
    int tx = tid & 15, ty = tid >> 4;
    int c0 = tx * 4, r0 = ty * 4;
    float acc[4][4] = {};
    #pragma unroll
    for (int k = 0; k < 64; k++) {
        float4 w = *(const float4*)&Wsh[k][c0];
        float x0 = Xs[r0][k], x1 = Xs[r0 + 1][k], x2 = Xs[r0 + 2][k], x3 = Xs[r0 + 3][k];
        acc[0][0] = fmaf(x0, w.x, acc[0][0]); acc[0][1] = fmaf(x0, w.y, acc[0][1]);
        acc[0][2] = fmaf(x0, w.z, acc[0][2]); acc[0][3] = fmaf(x0, w.w, acc[0][3]);
        acc[1][0] = fmaf(x1, w.x, acc[1][0]); acc[1][1] = fmaf(x1, w.y, acc[1][1]);
        acc[1][2] = fmaf(x1, w.z, acc[1][2]); acc[1][3] = fmaf(x1, w.w, acc[1][3]);
        acc[2][0] = fmaf(x2, w.x, acc[2][0]); acc[2][1] = fmaf(x2, w.y, acc[2][1]);
        acc[2][2] = fmaf(x2, w.z, acc[2][2]); acc[2][3] = fmaf(x2, w.w, acc[2][3]);
        acc[3][0] = fmaf(x3, w.x, acc[3][0]); acc[3][1] = fmaf(x3, w.y, acc[3][1]);
        acc[3][2] = fmaf(x3, w.z, acc[3][2]); acc[3][3] = fmaf(x3, w.w, acc[3][3]);
    }
    #pragma unroll
    for (int i = 0; i < 4; i++)
        *(float4*)&Y[((size_t)(row0 + r0 + i)) * 64 + c0] =
            make_float4(acc[i][0], acc[i][1], acc[i][2], acc[i][3]);
}

// ================== MEGA: single-pass direct-exp softmax (scores are O(1) bounded) ==========
__global__ void __launch_bounds__(512, 2) mega(
        int npBlocks, int ntfA,
        const int* rp1, const int* cs1, const float* ss1, const float* sd1,
        const float* X1, const float* W1,
        const int* rp2, const int* cs2, const float* ss2, const float* sd2,
        const float* X2, const float* W2,
        const float* b1, const float* b2, float* Yp, int relu,
        const float* pv0, float* po0, const float* pv1, float* po1,
        const float* pv2, float* po2, const float* pv3, float* po3,
        const float* Wn0, float* hsOut0, const float* Wn1, float* hsOut1,
        const int* rpA, const int* csA, const float* ssA, const float* sdA,
        const float* hsA, const float* bA, float* YA,
        const float* vA0, float* oA0, const float* vA1, float* oA1,
        const int* rpB, const int* csB, const float* ssB, const float* sdB,
        const float* hsB, const float* bB, float* YB,
        const float* vB0, float* oB0, const float* vB1, float* oB1) {
    __shared__ float Zs[64 * 68];
    __shared__ float Wsh[64][68];
    int tid = threadIdx.x;

    if ((int)blockIdx.x < npBlocks) {
        // ---------------- p-part: 64 rows, 8 lanes/row (4 col x 2 edge-subgroups) ----------
        int row0 = blockIdx.x * 64;
        int g8 = tid >> 3, l8 = tid & 7;
        int gl = l8 & 3, sg = l8 >> 2;
        int tx = tid & 15, ty = tid >> 4;
        int c0 = tx * 4, r0 = ty * 2;
        float acc[2][4] = {};
        int d = row0 + g8;
        for (int p = 0; p < 2; p++) {
            const int* rp = p ? rp2 : rp1;
            const int* cs = p ? cs2 : cs1;
            const float* ss = p ? ss2 : ss1;
            const float* sd = p ? sd2 : sd1;
            const float* X = p ? X2 : X1;
            const float* W = p ? W2 : W1;
            const float4* W4 = (const float4*)W;
            for (int i = tid; i < 1024; i += 512) {
                float4 v = W4[i];
                int r = i >> 4, c = (i & 15) * 4;
                Wsh[r][c] = v.x; Wsh[r][c + 1] = v.y; Wsh[r][c + 2] = v.z; Wsh[r][c + 3] = v.w;
            }
            int beg = rp[d], end = rp[d + 1];
            float sdv = sd[d];
            float s = 0.f;
            float4 a0 = {0,0,0,0}, a1 = {0,0,0,0}, a2 = {0,0,0,0}, a3 = {0,0,0,0};
            const float4* H4 = (const float4*)X;
            #pragma unroll 2
            for (int j = beg + sg; j < end; j += 2) {
                int src = cs[j];
                float t = ss[src] + sdv;
                t = t > 0.f ? t : 0.2f * t;
                float ex = __expf(t);
                s += ex;
                size_t hb = (size_t)src * 16 + gl * 4;
                float4 h0 = H4[hb], h1 = H4[hb + 1], h2 = H4[hb + 2], h3 = H4[hb + 3];
                a0.x = fmaf(ex, h0.x, a0.x); a0.y = fmaf(ex, h0.y, a0.y);
                a0.z = fmaf(ex, h0.z, a0.z); a0.w = fmaf(ex, h0.w, a0.w);
                a1.x = fmaf(ex, h1.x, a1.x); a1.y = fmaf(ex, h1.y, a1.y);
                a1.z = fmaf(ex, h1.z, a1.z); a1.w = fmaf(ex, h1.w, a1.w);
                a2.x = fmaf(ex, h2.x, a2.x); a2.y = fmaf(ex, h2.y, a2.y);
                a2.z = fmaf(ex, h2.z, a2.z); a2.w = fmaf(ex, h2.w, a2.w);
                a3.x = fmaf(ex, h3.x, a3.x); a3.y = fmaf(ex, h3.y, a3.y);
                a3.z = fmaf(ex, h3.z, a3.z); a3.w = fmaf(ex, h3.w, a3.w);
            }
            s += __shfl_xor_sync(FULLMASK, s, 4);
            a0.x += __shfl_xor_sync(FULLMASK, a0.x, 4); a0.y += __shfl_xor_sync(FULLMASK, a0.y, 4);
            a0.z += __shfl_xor_sync(FULLMASK, a0.z, 4); a0.w += __shfl_xor_sync(FULLMASK, a0.w, 4);
            a1.x += __shfl_xor_sync(FULLMASK, a1.x, 4); a1.y += __shfl_xor_sync(FULLMASK, a1.y, 4);
            a1.z += __shfl_xor_sync(FULLMASK, a1.z, 4); a1.w += __shfl_xor_sync(FULLMASK, a1.w, 4);
            a2.x += __shfl_xor_sync(FULLMASK, a2.x, 4); a2.y += __shfl_xor_sync(FULLMASK, a2.y, 4);
            a2.z += __shfl_xor_sync(FULLMASK, a2.z, 4); a2.w += __shfl_xor_sync(FULLMASK, a2.w, 4);
            a3.x += __shfl_xor_sync(FULLMASK, a3.x, 4); a3.y += __shfl_xor_sync(FULLMASK, a3.y, 4);
            a3.z += __shfl_xor_sync(FULLMASK, a3.z, 4); a3.w += __shfl_xor_sync(FULLMASK, a3.w, 4);
            float inv = s > 0.f ? 1.f / s : 0.f;
            if (sg == 0) {
                float4* Zr = (float4*)&Zs[g8 * 68];
                Zr[gl * 4]     = make_float4(a0.x * inv, a0.y * inv, a0.z * inv, a0.w * inv);
                Zr[gl * 4 + 1] = make_float4(a1.x * inv, a1.y * inv, a1.z * inv, a1.w * inv);
                Zr[gl * 4 + 2] = make_float4(a2.x * inv, a2.y * inv, a2.z * inv, a2.w * inv);
                Zr[gl * 4 + 3] = make_float4(a3.x * inv, a3.y * inv, a3.z * inv, a3.w * inv);
            }
            __syncthreads();
            #pragma unroll
            for (int k = 0; k < 64; k++) {
                float4 wv = *(const float4*)&Wsh[k][c0];
                float x0 = Zs[r0 * 68 + k], x1 = Zs[(r0 + 1) * 68 + k];
                acc[0][0] = fmaf(x0, wv.x, acc[0][0]); acc[0][1] = fmaf(x0, wv.y, acc[0][1]);
                acc[0][2] = fmaf(x0, wv.z, acc[0][2]); acc[0][3] = fmaf(x0, wv.w, acc[0][3]);
                acc[1][0] = fmaf(x1, wv.x, acc[1][0]); acc[1][1] = fmaf(x1, wv.y, acc[1][1]);
                acc[1][2] = fmaf(x1, wv.z, acc[1][2]); acc[1][3] = fmaf(x1, wv.w, acc[1][3]);
            }
            __syncthreads();
        }
        #pragma unroll
        for (int i = 0; i < 2; i++)
            #pragma unroll
            for (int c = 0; c < 4; c++) {
                float v = acc[i][c] + b1[c0 + c] + b2[c0 + c];
                if (relu) v = fmaxf(v, 0.f);
                Zs[(r0 + i) * 68 + c0 + c] = v;
            }
        __syncthreads();
        float4 ot[2];
        const float4* Zr = (const float4*)&Zs[g8 * 68];
        ot[0] = Zr[l8 * 2]; ot[1] = Zr[l8 * 2 + 1];
        float4* Yr = (float4*)&Yp[(size_t)d * 64];
        Yr[l8 * 2] = ot[0]; Yr[l8 * 2 + 1] = ot[1];
#define PDOT(v, o) if (v) { \
        const float4* V4 = (const float4*)v; \
        float4 vv0 = V4[l8 * 2], vv1 = V4[l8 * 2 + 1]; \
        float dd = ot[0].x * vv0.x + ot[0].y * vv0.y + ot[0].z * vv0.z + ot[0].w * vv0.w \
                 + ot[1].x * vv1.x + ot[1].y * vv1.y + ot[1].z * vv1.z + ot[1].w * vv1.w; \
        dd += __shfl_xor_sync(FULLMASK, dd, 1); \
        dd += __shfl_xor_sync(FULLMASK, dd, 2); \
        dd += __shfl_xor_sync(FULLMASK, dd, 4); \
        if (l8 == 0) o[d] = dd; }
        PDOT(pv0, po0)
        PDOT(pv1, po1)
        PDOT(pv2, po2)
        PDOT(pv3, po3)
#undef PDOT
        // ---- hs epilogue ----
        if (Wn0) {
            for (int p = 0; p < 2; p++) {
                const float* Wn = p ? Wn1 : Wn0;
                float* hsO = p ? hsOut1 : hsOut0;
                const float4* Wn4 = (const float4*)Wn;
                __syncthreads();
                for (int i = tid; i < 1024; i += 512) {
                    float4 v = Wn4[i];
                    int r = i >> 4, c = (i & 15) * 4;
                    Wsh[r][c] = v.x; Wsh[r][c + 1] = v.y; Wsh[r][c + 2] = v.z; Wsh[r][c + 3] = v.w;
                }
                __syncthreads();
                float ea[2][4] = {};
                #pragma unroll
                for (int k = 0; k < 64; k++) {
                    float4 wv = *(const float4*)&Wsh[k][c0];
                    float x0 = Zs[r0 * 68 + k], x1 = Zs[(r0 + 1) * 68 + k];
                    ea[0][0] = fmaf(x0, wv.x, ea[0][0]); ea[0][1] = fmaf(x0, wv.y, ea[0][1]);
                    ea[0][2] = fmaf(x0, wv.z, ea[0][2]); ea[0][3] = fmaf(x0, wv.w, ea[0][3]);
                    ea[1][0] = fmaf(x1, wv.x, ea[1][0]); ea[1][1] = fmaf(x1, wv.y, ea[1][1]);
                    ea[1][2] = fmaf(x1, wv.z, ea[1][2]); ea[1][3] = fmaf(x1, wv.w, ea[1][3]);
                }
                #pragma unroll
                for (int i = 0; i < 2; i++)
                    *(float4*)&hsO[((size_t)(row0 + r0 + i)) * 64 + c0] =
                        make_float4(ea[i][0], ea[i][1], ea[i][2], ea[i][3]);
            }
        }
    } else {
        // ---------------- tf-part: 4 lanes/row, single-pass direct-exp ----------------
        int tfIdx = blockIdx.x - npBlocks;
        bool isA = tfIdx < ntfA;
        int row0 = (isA ? tfIdx : tfIdx - ntfA) * 128;
        const int* rp = isA ? rpA : rpB;
        const int* cs = isA ? csA : csB;
        const float* ss = isA ? ssA : ssB;
        const float* sd = isA ? sdA : sdB;
        const float* hs = isA ? hsA : hsB;
        const float* b = isA ? bA : bB;
        float* Y = isA ? YA : YB;
        const float* v0 = isA ? vA0 : vB0;  float* o0 = isA ? oA0 : oB0;
        const float* v1 = isA ? vA1 : vB1;  float* o1 = isA ? oA1 : oB1;

        int g = tid >> 2, gl = tid & 3;
        int d = row0 + g;
        int beg = rp[d], end = rp[d + 1];
        float sdv = sd[d];
        float s = 0.f;
        float4 a0 = {0,0,0,0}, a1 = {0,0,0,0}, a2 = {0,0,0,0}, a3 = {0,0,0,0};
        const float4* H4 = (const float4*)hs;
        #pragma unroll 2
        for (int j = beg; j < end; j++) {
            int src = cs[j];
            float t = ss[src] + sdv;
            t = t > 0.f ? t : 0.2f * t;
            float ex = __expf(t);
            s += ex;
            size_t hb = (size_t)src * 16 + gl * 4;
            float4 h0 = H4[hb], h1 = H4[hb + 1], h2 = H4[hb + 2], h3 = H4[hb + 3];
            a0.x = fmaf(ex, h0.x, a0.x); a0.y = fmaf(ex, h0.y, a0.y);
            a0.z = fmaf(ex, h0.z, a0.z); a0.w = fmaf(ex, h0.w, a0.w);
            a1.x = fmaf(ex, h1.x, a1.x); a1.y = fmaf(ex, h1.y, a1.y);
            a1.z = fmaf(ex, h1.z, a1.z); a1.w = fmaf(ex, h1.w, a1.w);
            a2.x = fmaf(ex, h2.x, a2.x); a2.y = fmaf(ex, h2.y, a2.y);
            a2.z = fmaf(ex, h2.z, a2.z); a2.w = fmaf(ex, h2.w, a2.w);
            a3.x = fmaf(ex, h3.x, a3.x); a3.y = fmaf(ex, h3.y, a3.y);
            a3.z = fmaf(ex, h3.z, a3.z); a3.w = fmaf(ex, h3.w, a3.w);
        }
        float inv = s > 0.f ? 1.f / s : 0.f;
        const float4* B4 = (const float4*)b;
        float4 bb0 = B4[gl * 4], bb1 = B4[gl * 4 + 1], bb2 = B4[gl * 4 + 2], bb3 = B4[gl * 4 + 3];
        float4 ot[4];
        ot[0] = make_float4(a0.x * inv + bb0.x, a0.y * inv + bb0.y, a0.z * inv + bb0.z, a0.w * inv + bb0.w);
        ot[1] = make_float4(a1.x * inv + bb1.x, a1.y * inv + bb1.y, a1.z * inv + bb1.z, a1.w * inv + bb1.w);
        ot[2] = make_float4(a2.x * inv + bb2.x, a2.y * inv + bb2.y, a2.z * inv + bb2.z, a2.w * inv + bb2.w);
        ot[3] = make_float4(a3.x * inv + bb3.x, a3.y * inv + bb3.y, a3.z * inv + bb3.z, a3.w * inv + bb3.w);
        if (relu) {
            #pragma unroll
            for (int q = 0; q < 4; q++) {
                ot[q].x = fmaxf(ot[q].x, 0.f); ot[q].y = fmaxf(ot[q].y, 0.f);
                ot[q].z = fmaxf(ot[q].z, 0.f); ot[q].w = fmaxf(ot[q].w, 0.f);
            }
        }
        float4* Yr = (float4*)&Y[(size_t)d * 64];
        #pragma unroll
        for (int q = 0; q < 4; q++) Yr[gl * 4 + q] = ot[q];
#define TDOT(v, o) { \
        const float4* V4 = (const float4*)v; \
        float dd = 0.f; \
        _Pragma("unroll") \
        for (int q = 0; q < 4; q++) { \
            float4 vv = V4[gl * 4 + q]; \
            dd += ot[q].x * vv.x + ot[q].y * vv.y + ot[q].z * vv.z + ot[q].w * vv.w; \
        } \
        dd += __shfl_xor_sync(FULLMASK, dd, 1); \
        dd += __shfl_xor_sync(FULLMASK, dd, 2); \
        if (gl == 0) o[d] = dd; }
        TDOT(v0, o0)
        TDOT(v1, o1)
#undef TDOT
    }
}

// ---------------- fused pooling: 3 tables in one launch ----------------
__global__ void pool3(const float* __restrict__ xp, const float* __restrict__ xt,
                      const float* __restrict__ xf, float* __restrict__ rep) {
    int which = blockIdx.y;
    const float* x = (which == 0) ? xp : (which == 1) ? xt : xf;
    int npg = (which == 0) ? 64 : 512;
    int off = which * 192;
    int b = blockIdx.x;
    int t = threadIdx.x;            // 256
    int d = t & 63, c = t >> 6;
    const float* base = x + (size_t)b * npg * 64;
    float mx = -1e30f, mn = 1e30f, sm = 0.f;
    for (int n = c; n < npg; n += 4) {
        float v = base[(size_t)n * 64 + d];
        mx = fmaxf(mx, v); mn = fminf(mn, v); sm += v;
    }
    __shared__ float smx[4][64], smn[4][64], ssm[4][64];
    smx[c][d] = mx; smn[c][d] = mn; ssm[c][d] = sm;
    __syncthreads();
    if (c == 0) {
        for (int i = 1; i < 4; i++) {
            mx = fmaxf(mx, smx[i][d]); mn = fminf(mn, smn[i][d]); sm += ssm[i][d];
        }
        rep[b * 576 + off + d] = mx;
        rep[b * 576 + off + 64 + d] = mn;
        rep[b * 576 + off + 128 + d] = sm / (float)npg;
    }
}

// ---------------- fused actor head ----------------
__global__ void actor_head(const float* __restrict__ ap, const float* __restrict__ g,
                           const float* __restrict__ be, const float* __restrict__ Wa,
                           const float* __restrict__ ba, const int* __restrict__ part_id,
                           float* __restrict__ out) {
    __shared__ float sh[2];
    __shared__ float wa_s[128], g_s[64], be_s[64];
    int b = blockIdx.x, t = threadIdx.x;      // 64
    if (t < 64) {
        g_s[t] = g[t]; be_s[t] = be[t];
        wa_s[2 * t] = Wa[2 * t]; wa_s[2 * t + 1] = Wa[2 * t + 1];
    }
    __syncthreads();
    int n = b * 64 + t;
    const float4* A4 = (const float4*)&ap[(size_t)n * 64];
    float4 va[16];
    float sum = 0.f;
    #pragma unroll
    for (int q = 0; q < 16; q++) { va[q] = A4[q]; sum += va[q].x + va[q].y + va[q].z + va[q].w; }
    float mu = sum * (1.f / 64.f);
    float vs = 0.f;
    #pragma unroll
    for (int q = 0; q < 16; q++) {
        float dx = va[q].x - mu, dy = va[q].y - mu, dz = va[q].z - mu, dw = va[q].w - mu;
        vs += dx * dx + dy * dy + dz * dz + dw * dw;
    }
    float rs = rsqrtf(vs * (1.f / 64.f) + 1e-5f);
    float r0 = 0.f, r1 = 0.f;
    #pragma unroll
    for (int q = 0; q < 16; q++) {
        float y0 = (va[q].x - mu) * rs * g_s[4 * q]     + be_s[4 * q];
        float y1 = (va[q].y - mu) * rs * g_s[4 * q + 1] + be_s[4 * q + 1];
        float y2 = (va[q].z - mu) * rs * g_s[4 * q + 2] + be_s[4 * q + 2];
        float y3 = (va[q].w - mu) * rs * g_s[4 * q + 3] + be_s[4 * q + 3];
        r0 += y0 * wa_s[(4 * q) * 2] + y1 * wa_s[(4 * q + 1) * 2]
            + y2 * wa_s[(4 * q + 2) * 2] + y3 * wa_s[(4 * q + 3) * 2];
        r1 += y0 * wa_s[(4 * q) * 2 + 1] + y1 * wa_s[(4 * q + 1) * 2 + 1]
            + y2 * wa_s[(4 * q + 2) * 2 + 1] + y3 * wa_s[(4 * q + 3) * 2 + 1];
    }
    r0 += ba[0]; r1 += ba[1];
    float v = r0;
    for (int o = 16; o; o >>= 1) v = fmaxf(v, __shfl_xor_sync(FULLMASK, v, o));
    if ((t & 31) == 0) sh[t >> 5] = v;
    __syncthreads();
    float m0 = fmaxf(sh[0], sh[1]);
    __syncthreads();
    v = r1;
    for (int o = 16; o; o >>= 1) v = fmaxf(v, __shfl_xor_sync(FULLMASK, v, o));
    if ((t & 31) == 0) sh[t >> 5] = v;
    __syncthreads();
    float m1 = fmaxf(sh[0], sh[1]);
    __syncthreads();
    float e0 = expf(r0 - m0), e1 = expf(r1 - m1);
    v = e0;
    for (int o = 16; o; o >>= 1) v += __shfl_xor_sync(FULLMASK, v, o);
    if ((t & 31) == 0) sh[t >> 5] = v;
    __syncthreads();
    float s0 = sh[0] + sh[1];
    __syncthreads();
    v = e1;
    for (int o = 16; o; o >>= 1) v += __shfl_xor_sync(FULLMASK, v, o);
    if ((t & 31) == 0) sh[t >> 5] = v;
    __syncthreads();
    float s1 = sh[0] + sh[1];
    int p = part_id[n];
    out[b * 128 + p] = e0 / s0;
    out[b * 128 + 64 + p] = e1 / s1;
}

// ---------------- fused value head ----------------
__global__ void vhead(const float* __restrict__ rep,
                      const float* __restrict__ W1, const float* __restrict__ b1,
                      const float* __restrict__ W2, const float* __restrict__ b2,
                      const float* __restrict__ Wo, const float* __restrict__ bo,
                      float* __restrict__ V) {
    __shared__ float s[576];
    __shared__ float h[64];
    __shared__ float sh[2];
    int b = blockIdx.x, j = threadIdx.x;      // 64
    for (int k = j; k < 576; k += 64) s[k] = rep[b * 576 + k];
    __syncthreads();
    float acc = b1[j];
    for (int k = 0; k < 576; k++) acc = fmaf(s[k], W1[k * 64 + j], acc);
    acc = 0.5f * acc * (1.f + erff(acc * 0.70710678118654752f));
    h[j] = acc;
    __syncthreads();
    float acc2 = b2[j];
    #pragma unroll 8
    for (int k = 0; k < 64; k++) acc2 = fmaf(h[k], W2[k * 64 + j], acc2);
    acc2 = 0.5f * acc2 * (1.f + erff(acc2 * 0.70710678118654752f));
    float part = acc2 * Wo[j];
    for (int o = 16; o; o >>= 1) part += __shfl_xor_sync(FULLMASK, part, o);
    if ((j & 31) == 0) sh[j >> 5] = part;
    __syncthreads();
    if (j == 0) V[b] = tanhf(sh[0] + sh[1] + bo[0]);
}

// ---------------- host ----------------
#define SYMF(p, s) do { void* _q; cudaGetSymbolAddress(&_q, s); p = (float*)_q; } while (0)
#define SYMI(p, s) do { void* _q; cudaGetSymbolAddress(&_q, s); p = (int*)_q; } while (0)

extern "C" void kernel_launch(void* const* d_in, const int* in_sizes, int n_in,
                              void* d_out, int out_size) {
    const float* mass      = (const float*)d_in[0];
    const int*   pstate    = (const int*)d_in[1];
    const float* torque_x  = (const float*)d_in[2];
    const float* force_x   = (const float*)d_in[3];
    const int* e_pt_src = (const int*)d_in[4];
    const int* e_pt_dst = (const int*)d_in[5];
    const int* e_tp_src = (const int*)d_in[6];
    const int* e_tp_dst = (const int*)d_in[7];
    const int* e_pf_src = (const int*)d_in[8];
    const int* e_pf_dst = (const int*)d_in[9];
    const int* e_fp_src = (const int*)d_in[10];
    const int* e_fp_dst = (const int*)d_in[11];
    const int* part_id  = (const int*)d_in[13];
    const float* embW   = (const float*)d_in[14];
    const float* embS   = (const float*)d_in[15];
    const float* W_src  = (const float*)d_in[16];
    const float* W_dst  = (const float*)d_in[17];
    const float* a_src  = (const float*)d_in[18];
    const float* a_dst  = (const float*)d_in[19];
    const float* b_conv = (const float*)d_in[20];
    const float* ln_g   = (const float*)d_in[21];
    const float* ln_b   = (const float*)d_in[22];
    const float* outaW  = (const float*)d_in[23];
    const float* outab  = (const float*)d_in[24];
    const float* innW   = (const float*)d_in[25];
    const float* innb   = (const float*)d_in[26];
    const float* fulW   = (const float*)d_in[27];
    const float* fulb   = (const float*)d_in[28];
    const float* outW   = (const float*)d_in[29];
    const float* outb   = (const float*)d_in[30];
    float* out = (float*)d_out;

    float *xp, *xt, *xf, *ap, *hs0, *hs1;
    float *ss_pt, *ss_pf, *sd_tp, *sd_fp, *ss_tp, *sd_pt, *ss_fp, *sd_pf;
    float *wsv, *wdv, *rep;
    int *rp_pt, *rp_pf, *rp_tp, *rp_fp, *cs_pt, *cs_tp, *cs_pf, *cs_fp, *cnt, *aux;
    SYMF(xp, g_xp); SYMF(xt, g_xt); SYMF(xf, g_xf); SYMF(ap, g_ap);
    SYMF(hs0, g_hs0); SYMF(hs1, g_hs1);
    SYMF(ss_pt, g_ss_pt); SYMF(ss_pf, g_ss_pf); SYMF(sd_tp, g_sd_tp); SYMF(sd_fp, g_sd_fp);
    SYMF(ss_tp, g_ss_tp); SYMF(sd_pt, g_sd_pt); SYMF(ss_fp, g_ss_fp); SYMF(sd_pf, g_sd_pf);
    SYMF(wsv, g_wsv); SYMF(wdv, g_wdv); SYMF(rep, g_rep);
    SYMI(rp_pt, g_rp_pt); SYMI(rp_pf, g_rp_pf); SYMI(rp_tp, g_rp_tp); SYMI(rp_fp, g_rp_fp);
    SYMI(cs_pt, g_cs_pt); SYMI(cs_tp, g_cs_tp); SYMI(cs_pf, g_cs_pf); SYMI(cs_fp, g_cs_fp);
    SYMI(cnt, g_cnt); SYMI(aux, g_aux);

    // batched CSR build (parallel 3-phase scan)
    zero4<<<(4 * NTC) / 256, 256>>>(cnt);
    { dim3 g(EC / 256, 4); hist4<<<g, 256>>>(e_pt_dst, e_tp_dst, e_pf_dst, e_fp_dst, cnt); }
    { dim3 g(128, 4); scanA<<<g, 1024>>>(cnt, rp_pt, rp_tp, rp_pf, rp_fp, aux); }
    scanB<<<1, 512>>>(aux);
    { dim3 g(128, 4); scanC<<<g, 1024>>>(cnt, rp_pt, rp_tp, rp_pf, rp_fp, aux); }
    { dim3 g(EC / 256, 4);
      scatter4<<<g, 256>>>(e_pt_src, e_pt_dst, e_tp_src, e_tp_dst,
                           e_pf_src, e_pf_dst, e_fp_src, e_fp_dst,
                           rp_pt, rp_tp, rp_pf, rp_fp, cnt,
                           cs_pt, cs_tp, cs_pf, cs_fp); }

    // score vectors; embed; layer-0 score dots; bootstrap hs (parity 0)
    vec_all<<<10, 256>>>(W_src, a_src, W_dst, a_dst, wsv, wdv);
    dot4<<<(NTC * 32) / 256, 256>>>(torque_x, NTC,
         wsv + 1 * 64, ss_tp, wdv + 0 * 64, sd_pt, nullptr, nullptr, nullptr, nullptr);
    dot4<<<(NFC * 32) / 256, 256>>>(force_x, NFC,
         wsv + 3 * 64, ss_fp, wdv + 2 * 64, sd_pf, nullptr, nullptr, nullptr, nullptr);
    embed_k<<<(NPC * 64) / 256, 256>>>(mass, pstate, embW, embS, xp);
    dot4<<<(NPC * 32) / 256, 256>>>(xp, NPC,
         wsv + 0 * 64, ss_pt, wsv + 2 * 64, ss_pf,
         wdv + 1 * 64, sd_tp, wdv + 3 * 64, sd_fp);
    mm_hs<<<2 * (NPC / 64), 256>>>(xp, W_src + 0 * 4096, hs0, W_src + 2 * 4096, hs1);

    for (int l = 0; l < 5; l++) {
        int ci = l & 1, ni = (l + 1) & 1;
        const float* xti = (l == 0) ? torque_x : xt + (size_t)ni * NTC * 64;
        const float* xfi = (l == 0) ? force_x  : xf + (size_t)ni * NFC * 64;
        float* xto = xt + (size_t)ci * NTC * 64;
        float* xfo = xf + (size_t)ci * NFC * 64;
        const float* Wl = W_src + (size_t)l * 4 * 4096;
        const float* bl = b_conv + (size_t)l * 4 * 64;
        int relu = (l < 3) ? 1 : 0;
        int actor = (l == 4);
        const float* nwsv = wsv + (size_t)(l + 1) * 4 * 64;
        const float* nwdv = wdv + (size_t)(l + 1) * 4 * 64;
        const float* c_ss_pt = ss_pt + ci * NPC;  float* n_ss_pt = ss_pt + ni * NPC;
        const float* c_ss_pf = ss_pf + ci * NPC;  float* n_ss_pf = ss_pf + ni * NPC;
        const float* c_sd_tp = sd_tp + ci * NPC;  float* n_sd_tp = sd_tp + ni * NPC;
        const float* c_sd_fp = sd_fp + ci * NPC;  float* n_sd_fp = sd_fp + ni * NPC;
        const float* c_ss_tp = ss_tp + ci * NTC;  float* n_ss_tp = ss_tp + ni * NTC;
        const float* c_sd_pt = sd_pt + ci * NTC;  float* n_sd_pt = sd_pt + ni * NTC;
        const float* c_ss_fp = ss_fp + ci * NFC;  float* n_ss_fp = ss_fp + ni * NFC;
        const float* c_sd_pf = sd_pf + ci * NFC;  float* n_sd_pf = sd_pf + ni * NFC;
        const float* hs0c = hs0 + (size_t)ci * NPC * 64;
        const float* hs1c = hs1 + (size_t)ci * NPC * 64;
        float* hs0n = hs0 + (size_t)ni * NPC * 64;
        float* hs1n = hs1 + (size_t)ni * NPC * 64;
        const float* Wnext = W_src + (size_t)(l + 1) * 4 * 4096;
        int doEpi = (l < 3);

        if (!actor) {
            mega<<<NPC / 64 + NTC / 128 + NFC / 128, 512>>>(
                NPC / 64, NTC / 128,
                rp_tp, cs_tp, c_ss_tp, c_sd_tp, xti, Wl + 1 * 4096,
                rp_fp, cs_fp, c_ss_fp, c_sd_fp, xfi, Wl + 3 * 4096,
                bl + 1 * 64, bl + 3 * 64, xp, relu,
                nwsv + 0 * 64, n_ss_pt, nwsv + 2 * 64, n_ss_pf,
                nwdv + 1 * 64, n_sd_tp, nwdv + 3 * 64, n_sd_fp,
                doEpi ? (Wnext + 0 * 4096) : nullptr, hs0n,
                doEpi ? (Wnext + 2 * 4096) : nullptr, hs1n,
                rp_pt, cs_pt, c_ss_pt, c_sd_pt, hs0c, bl + 0 * 64, xto,
                nwsv + 1 * 64, n_ss_tp, nwdv + 0 * 64, n_sd_pt,
                rp_pf, cs_pf, c_ss_pf, c_sd_pf, hs1c, bl + 2 * 64, xfo,
                nwsv + 3 * 64, n_ss_fp, nwdv + 2 * 64, n_sd_pf);
        } else {
            mega<<<NPC / 64, 512>>>(
                NPC / 64, 0,
                rp_tp, cs_tp, c_ss_tp, c_sd_tp, xti, Wl + 1 * 4096,
                rp_fp, cs_fp, c_ss_fp, c_sd_fp, xfi, Wl + 3 * 4096,
                bl + 1 * 64, bl + 3 * 64, ap, 0,
                nullptr, nullptr, nullptr, nullptr,
                nullptr, nullptr, nullptr, nullptr,
                nullptr, nullptr, nullptr, nullptr,
                nullptr, nullptr, nullptr, nullptr, nullptr, nullptr, nullptr,
                nullptr, nullptr, nullptr, nullptr,
                nullptr, nullptr, nullptr, nullptr, nullptr, nullptr, nullptr,
                nullptr, nullptr, nullptr, nullptr);
        }
    }

    // fused pooling: l=3 wrote xt/xf parity 1; xp in place
    { dim3 g(BC, 3); pool3<<<g, 256>>>(xp, xt + (size_t)NTC * 64, xf + (size_t)NFC * 64, rep); }

    // fused heads
    actor_head<<<BC, 64>>>(ap, ln_g, ln_b, outaW, outab, part_id, out);
    vhead<<<BC, 64>>>(rep, innW, innb, fulW, fulb, outW, outb, out + BC * 128);
}

// round 17
// speedup vs baseline: 1.4317x; 1.1965x over previous
#include <cuda_runtime.h>
#include <math.h>

#define NPC 16384
#define NTC 131072
#define NFC 131072
#define EC  262144
#define BC  256
#define FULLMASK 0xffffffffu

// ---------------- device scratch ----------------
__device__ float g_xp[NPC * 64];
__device__ float g_xt[2][NTC * 64];
__device__ float g_xf[2][NFC * 64];
__device__ float g_ap[NPC * 64];
__device__ float g_hs0[2][NPC * 64];
__device__ float g_hs1[2][NPC * 64];
__device__ float g_ss_pt[2][NPC], g_ss_pf[2][NPC], g_sd_tp[2][NPC], g_sd_fp[2][NPC];
__device__ float g_ss_tp[2][NTC], g_sd_pt[2][NTC];
__device__ float g_ss_fp[2][NFC], g_sd_pf[2][NFC];
__device__ float g_wsv[5 * 4 * 64], g_wdv[5 * 4 * 64];
__device__ int g_rp_pt[NTC + 1], g_rp_pf[NFC + 1];
__device__ int g_rp_tp[NPC + 1], g_rp_fp[NPC + 1];
__device__ int g_cs_pt[EC], g_cs_tp[EC], g_cs_pf[EC], g_cs_fp[EC];
__device__ int g_cnt[4 * NTC];
__device__ int g_aux[520];
__device__ float g_rep[BC * 576];

// ---------------- batched CSR build ----------------
__global__ void zero4(int* c) {
    int i = blockIdx.x * blockDim.x + threadIdx.x;
    if (i < 4 * NTC) c[i] = 0;
}

__global__ void hist4(const int* __restrict__ d0, const int* __restrict__ d1,
                      const int* __restrict__ d2, const int* __restrict__ d3,
                      int* __restrict__ cnt) {
    int t = blockIdx.y;
    const int* d = (t == 0) ? d0 : (t == 1) ? d1 : (t == 2) ? d2 : d3;
    int* c = cnt + t * NTC;
    int i = blockIdx.x * blockDim.x + threadIdx.x;
    if (i < EC) atomicAdd(&c[d[i]], 1);
}

__global__ void __launch_bounds__(1024) scanA(const int* __restrict__ cnt,
        int* rp0, int* rp1, int* rp2, int* rp3, int* __restrict__ aux) {
    __shared__ int ws[32];
    int t = blockIdx.y;
    int* rowptr = (t == 0) ? rp0 : (t == 1) ? rp1 : (t == 2) ? rp2 : rp3;
    int n = (t == 0) ? NTC : (t == 1) ? NPC : (t == 2) ? NFC : NPC;
    const int* deg = cnt + t * NTC;
    int tid = threadIdx.x, lane = tid & 31, wid = tid >> 5;
    int i = blockIdx.x * 1024 + tid;
    int v = (i < n) ? deg[i] : 0;
    int x = v;
    #pragma unroll
    for (int off = 1; off < 32; off <<= 1) {
        int y = __shfl_up_sync(FULLMASK, x, off);
        if (lane >= off) x += y;
    }
    if (lane == 31) ws[wid] = x;
    __syncthreads();
    if (tid < 32) {
        int s = ws[tid];
        #pragma unroll
        for (int off = 1; off < 32; off <<= 1) {
            int y = __shfl_up_sync(FULLMASK, s, off);
            if (tid >= off) s += y;
        }
        ws[tid] = s;
    }
    __syncthreads();
    int excl = x - v + (wid ? ws[wid - 1] : 0);
    if (i < n) rowptr[i] = excl;
    if (tid == 0) aux[t * 128 + blockIdx.x] = ws[31];
}

__global__ void __launch_bounds__(512) scanB(int* __restrict__ aux) {
    __shared__ int wsum[16];
    int tid = threadIdx.x;
    int t = tid >> 7, idx = tid & 127;
    int lane = tid & 31, wid = tid >> 5;
    int v = aux[t * 128 + idx];
    int x = v;
    #pragma unroll
    for (int off = 1; off < 32; off <<= 1) {
        int y = __shfl_up_sync(FULLMASK, x, off);
        if (lane >= off) x += y;
    }
    if (lane == 31) wsum[wid] = x;
    __syncthreads();
    int offsum = 0;
    for (int w = t * 4; w < wid; w++) offsum += wsum[w];
    int excl = x - v + offsum;
    aux[t * 128 + idx] = excl;
    if (idx == 127) aux[512 + t] = excl + v;
}

__global__ void __launch_bounds__(1024) scanC(int* __restrict__ cnt,
        int* rp0, int* rp1, int* rp2, int* rp3, const int* __restrict__ aux) {
    int t = blockIdx.y;
    int* rowptr = (t == 0) ? rp0 : (t == 1) ? rp1 : (t == 2) ? rp2 : rp3;
    int n = (t == 0) ? NTC : (t == 1) ? NPC : (t == 2) ? NFC : NPC;
    int i = blockIdx.x * 1024 + threadIdx.x;
    if (i < n) {
        rowptr[i] += aux[t * 128 + blockIdx.x];
        cnt[t * NTC + i] = 0;
    }
    if (i == 0) rowptr[n] = aux[512 + t];
}

__global__ void scatter4(const int* __restrict__ s0, const int* __restrict__ d0,
                         const int* __restrict__ s1, const int* __restrict__ d1,
                         const int* __restrict__ s2, const int* __restrict__ d2,
                         const int* __restrict__ s3, const int* __restrict__ d3,
                         const int* rp0, const int* rp1, const int* rp2, const int* rp3,
                         int* __restrict__ cnt,
                         int* c0, int* c1, int* c2, int* c3) {
    int t = blockIdx.y;
    const int* src = (t == 0) ? s0 : (t == 1) ? s1 : (t == 2) ? s2 : s3;
    const int* dst = (t == 0) ? d0 : (t == 1) ? d1 : (t == 2) ? d2 : d3;
    const int* rp  = (t == 0) ? rp0 : (t == 1) ? rp1 : (t == 2) ? rp2 : rp3;
    int* csr = (t == 0) ? c0 : (t == 1) ? c1 : (t == 2) ? c2 : c3;
    int* cur = cnt + t * NTC;
    int i = blockIdx.x * blockDim.x + threadIdx.x;
    if (i >= EC) return;
    int d = dst[i];
    int pos = rp[d] + atomicAdd(&cur[d], 1);
    csr[pos] = src[i];
}

// ---------------- score vectors for ALL layers ----------------
__global__ void vec_all(const float* __restrict__ Ws, const float* __restrict__ as,
                        const float* __restrict__ Wd, const float* __restrict__ ad,
                        float* __restrict__ wsv, float* __restrict__ wdv) {
    int idx = blockIdx.x * blockDim.x + threadIdx.x;
    if (idx >= 2 * 5 * 4 * 64) return;
    int which = idx >= 1280;
    int r = which ? idx - 1280 : idx;
    int i = r & 63, lt = r >> 6;
    const float* W = which ? Wd : Ws;
    const float* a = which ? ad : as;
    float* o = which ? wdv : wsv;
    float acc = 0.f;
    const float* wr = W + (size_t)(lt * 64 + i) * 64;
    const float* ar = a + lt * 64;
    #pragma unroll 8
    for (int j = 0; j < 64; j++) acc = fmaf(wr[j], ar[j], acc);
    o[r] = acc;
}

// ---------------- embed ----------------
__global__ void embed_k(const float* __restrict__ mass, const int* __restrict__ pstate,
                        const float* __restrict__ embW, const float* __restrict__ embS,
                        float* __restrict__ xp) {
    int idx = blockIdx.x * blockDim.x + threadIdx.x;
    if (idx >= NPC * 64) return;
    int n = idx >> 6, j = idx & 63;
    float v;
    if (j < 32) v = mass[n] * embW[j];
    else {
        int st = pstate[2 * n] + 2 * pstate[2 * n + 1];
        v = embS[st * 32 + (j - 32)];
    }
    xp[idx] = v;
}

// ---------------- up to 4 per-row dot products (layer-0 init) ----------------
__global__ void dot4(const float* __restrict__ X, int n,
                     const float* v0, float* o0, const float* v1, float* o1,
                     const float* v2, float* o2, const float* v3, float* o3) {
    int idx = blockIdx.x * blockDim.x + threadIdx.x;
    int w = idx >> 5;
    if (w >= n) return;
    int lane = idx & 31;
    float2 x = *(const float2*)&X[(size_t)w * 64 + lane * 2];
#define DODOT(v, o) if (v) { \
        float s = x.x * v[2 * lane] + x.y * v[2 * lane + 1]; \
        for (int off = 16; off; off >>= 1) s += __shfl_xor_sync(FULLMASK, s, off); \
        if (lane == 0) o[w] = s; }
    DODOT(v0, o0)
    DODOT(v1, o1)
    DODOT(v2, o2)
    DODOT(v3, o3)
#undef DODOT
}

// ---------------- bootstrap hs matmul ----------------
__global__ void __launch_bounds__(256) mm_hs(const float* __restrict__ X,
                                             const float* __restrict__ W0, float* __restrict__ Y0,
                                             const float* __restrict__ W1, float* __restrict__ Y1) {
    __shared__ float Xs[64][65];
    __shared__ float Wsh[64][68];
    int half = blockIdx.x >= (NPC / 64);
    int row0 = (half ? blockIdx.x - NPC / 64 : blockIdx.x) * 64;
    const float* W = half ? W1 : W0;
    float* Y = half ? Y1 : Y0;
    int tid = threadIdx.x;
    const float4* W4 = (const float4*)W;
    for (int i = tid; i < 1024; i += 256) {
        float4 v = W4[i];
        int r = i >> 4, c = (i & 15) * 4;
        Wsh[r][c] = v.x; Wsh[r][c + 1] = v.y; Wsh[r][c + 2] = v.z; Wsh[r][c + 3] = v.w;
    }
    const float4* X4 = (const float4*)(X + (size_t)row0 * 64);
    for (int i = tid; i < 1024; i += 256) {
        float4 v = X4[i];
        int r = i >> 4, c = (i & 15) * 4;
        Xs[r][c] = v.x; Xs[r][c + 1] = v.y; Xs[r][c + 2] = v.z; Xs[r][c + 3] = v.w;
    }
    __syncthreads();
    int tx = tid & 15, ty = tid >> 4;
    int c0 = tx * 4, r0 = ty * 4;
    float acc[4][4] = {};
    #pragma unroll
    for (int k = 0; k < 64; k++) {
        float4 w = *(const float4*)&Wsh[k][c0];
        float x0 = Xs[r0][k], x1 = Xs[r0 + 1][k], x2 = Xs[r0 + 2][k], x3 = Xs[r0 + 3][k];
        acc[0][0] = fmaf(x0, w.x, acc[0][0]); acc[0][1] = fmaf(x0, w.y, acc[0][1]);
        acc[0][2] = fmaf(x0, w.z, acc[0][2]); acc[0][3] = fmaf(x0, w.w, acc[0][3]);
        acc[1][0] = fmaf(x1, w.x, acc[1][0]); acc[1][1] = fmaf(x1, w.y, acc[1][1]);
        acc[1][2] = fmaf(x1, w.z, acc[1][2]); acc[1][3] = fmaf(x1, w.w, acc[1][3]);
        acc[2][0] = fmaf(x2, w.x, acc[2][0]); acc[2][1] = fmaf(x2, w.y, acc[2][1]);
        acc[2][2] = fmaf(x2, w.z, acc[2][2]); acc[2][3] = fmaf(x2, w.w, acc[2][3]);
        acc[3][0] = fmaf(x3, w.x, acc[3][0]); acc[3][1] = fmaf(x3, w.y, acc[3][1]);
        acc[3][2] = fmaf(x3, w.z, acc[3][2]); acc[3][3] = fmaf(x3, w.w, acc[3][3]);
    }
    #pragma unroll
    for (int i = 0; i < 4; i++)
        *(float4*)&Y[((size_t)(row0 + r0 + i)) * 64 + c0] =
            make_float4(acc[i][0], acc[i][1], acc[i][2], acc[i][3]);
}

// ================== MEGA: interleaved lane->column gather (1 line/row/instr) ==========
__global__ void __launch_bounds__(512, 2) mega(
        int npBlocks, int ntfA,
        const int* rp1, const int* cs1, const float* ss1, const float* sd1,
        const float* X1, const float* W1,
        const int* rp2, const int* cs2, const float* ss2, const float* sd2,
        const float* X2, const float* W2,
        const float* b1, const float* b2, float* Yp, int relu,
        const float* pv0, float* po0, const float* pv1, float* po1,
        const float* pv2, float* po2, const float* pv3, float* po3,
        const float* Wn0, float* hsOut0, const float* Wn1, float* hsOut1,
        const int* rpA, const int* csA, const float* ssA, const float* sdA,
        const float* hsA, const float* bA, float* YA,
        const float* vA0, float* oA0, const float* vA1, float* oA1,
        const int* rpB, const int* csB, const float* ssB, const float* sdB,
        const float* hsB, const float* bB, float* YB,
        const float* vB0, float* oB0, const float* vB1, float* oB1) {
    __shared__ float Zs[64 * 68];
    __shared__ float Wsh[64][68];
    int tid = threadIdx.x;

    if ((int)blockIdx.x < npBlocks) {
        // ---------------- p-part: 64 rows, 8 lanes/row (4 col x 2 edge-subgroups) ----------
        int row0 = blockIdx.x * 64;
        int g8 = tid >> 3, l8 = tid & 7;
        int gl = l8 & 3, sg = l8 >> 2;
        int tx = tid & 15, ty = tid >> 4;
        int c0 = tx * 4, r0 = ty * 2;
        float acc[2][4] = {};
        int d = row0 + g8;
        for (int p = 0; p < 2; p++) {
            const int* rp = p ? rp2 : rp1;
            const int* cs = p ? cs2 : cs1;
            const float* ss = p ? ss2 : ss1;
            const float* sd = p ? sd2 : sd1;
            const float* X = p ? X2 : X1;
            const float* W = p ? W2 : W1;
            const float4* W4 = (const float4*)W;
            for (int i = tid; i < 1024; i += 512) {
                float4 v = W4[i];
                int r = i >> 4, c = (i & 15) * 4;
                Wsh[r][c] = v.x; Wsh[r][c + 1] = v.y; Wsh[r][c + 2] = v.z; Wsh[r][c + 3] = v.w;
            }
            int beg = rp[d], end = rp[d + 1];
            float sdv = sd[d];
            float s = 0.f;
            float4 a0 = {0,0,0,0}, a1 = {0,0,0,0}, a2 = {0,0,0,0}, a3 = {0,0,0,0};
            const float4* H4 = (const float4*)X;
            #pragma unroll 2
            for (int j = beg + sg; j < end; j += 2) {
                int src = cs[j];
                float t = ss[src] + sdv;
                t = t > 0.f ? t : 0.2f * t;
                float ex = __expf(t);
                s += ex;
                size_t hb = (size_t)src * 16 + gl;     // interleaved: lane gl owns float4s {gl, 4+gl, 8+gl, 12+gl}
                float4 h0 = H4[hb], h1 = H4[hb + 4], h2 = H4[hb + 8], h3 = H4[hb + 12];
                a0.x = fmaf(ex, h0.x, a0.x); a0.y = fmaf(ex, h0.y, a0.y);
                a0.z = fmaf(ex, h0.z, a0.z); a0.w = fmaf(ex, h0.w, a0.w);
                a1.x = fmaf(ex, h1.x, a1.x); a1.y = fmaf(ex, h1.y, a1.y);
                a1.z = fmaf(ex, h1.z, a1.z); a1.w = fmaf(ex, h1.w, a1.w);
                a2.x = fmaf(ex, h2.x, a2.x); a2.y = fmaf(ex, h2.y, a2.y);
                a2.z = fmaf(ex, h2.z, a2.z); a2.w = fmaf(ex, h2.w, a2.w);
                a3.x = fmaf(ex, h3.x, a3.x); a3.y = fmaf(ex, h3.y, a3.y);
                a3.z = fmaf(ex, h3.z, a3.z); a3.w = fmaf(ex, h3.w, a3.w);
            }
            s += __shfl_xor_sync(FULLMASK, s, 4);
            a0.x += __shfl_xor_sync(FULLMASK, a0.x, 4); a0.y += __shfl_xor_sync(FULLMASK, a0.y, 4);
            a0.z += __shfl_xor_sync(FULLMASK, a0.z, 4); a0.w += __shfl_xor_sync(FULLMASK, a0.w, 4);
            a1.x += __shfl_xor_sync(FULLMASK, a1.x, 4); a1.y += __shfl_xor_sync(FULLMASK, a1.y, 4);
            a1.z += __shfl_xor_sync(FULLMASK, a1.z, 4); a1.w += __shfl_xor_sync(FULLMASK, a1.w, 4);
            a2.x += __shfl_xor_sync(FULLMASK, a2.x, 4); a2.y += __shfl_xor_sync(FULLMASK, a2.y, 4);
            a2.z += __shfl_xor_sync(FULLMASK, a2.z, 4); a2.w += __shfl_xor_sync(FULLMASK, a2.w, 4);
            a3.x += __shfl_xor_sync(FULLMASK, a3.x, 4); a3.y += __shfl_xor_sync(FULLMASK, a3.y, 4);
            a3.z += __shfl_xor_sync(FULLMASK, a3.z, 4); a3.w += __shfl_xor_sync(FULLMASK, a3.w, 4);
            float inv = s > 0.f ? 1.f / s : 0.f;
            if (sg == 0) {
                float4* Zr = (float4*)&Zs[g8 * 68];
                Zr[gl]      = make_float4(a0.x * inv, a0.y * inv, a0.z * inv, a0.w * inv);
                Zr[4 + gl]  = make_float4(a1.x * inv, a1.y * inv, a1.z * inv, a1.w * inv);
                Zr[8 + gl]  = make_float4(a2.x * inv, a2.y * inv, a2.z * inv, a2.w * inv);
                Zr[12 + gl] = make_float4(a3.x * inv, a3.y * inv, a3.z * inv, a3.w * inv);
            }
            __syncthreads();
            #pragma unroll
            for (int k = 0; k < 64; k++) {
                float4 wv = *(const float4*)&Wsh[k][c0];
                float x0 = Zs[r0 * 68 + k], x1 = Zs[(r0 + 1) * 68 + k];
                acc[0][0] = fmaf(x0, wv.x, acc[0][0]); acc[0][1] = fmaf(x0, wv.y, acc[0][1]);
                acc[0][2] = fmaf(x0, wv.z, acc[0][2]); acc[0][3] = fmaf(x0, wv.w, acc[0][3]);
                acc[1][0] = fmaf(x1, wv.x, acc[1][0]); acc[1][1] = fmaf(x1, wv.y, acc[1][1]);
                acc[1][2] = fmaf(x1, wv.z, acc[1][2]); acc[1][3] = fmaf(x1, wv.w, acc[1][3]);
            }
            __syncthreads();
        }
        #pragma unroll
        for (int i = 0; i < 2; i++)
            #pragma unroll
            for (int c = 0; c < 4; c++) {
                float v = acc[i][c] + b1[c0 + c] + b2[c0 + c];
                if (relu) v = fmaxf(v, 0.f);
                Zs[(r0 + i) * 68 + c0 + c] = v;
            }
        __syncthreads();
        float4 ot[2];
        const float4* Zr = (const float4*)&Zs[g8 * 68];
        ot[0] = Zr[l8]; ot[1] = Zr[8 + l8];
        float4* Yr = (float4*)&Yp[(size_t)d * 64];
        Yr[l8] = ot[0]; Yr[8 + l8] = ot[1];
#define PDOT(v, o) if (v) { \
        const float4* V4 = (const float4*)v; \
        float4 vv0 = V4[l8], vv1 = V4[8 + l8]; \
        float dd = ot[0].x * vv0.x + ot[0].y * vv0.y + ot[0].z * vv0.z + ot[0].w * vv0.w \
                 + ot[1].x * vv1.x + ot[1].y * vv1.y + ot[1].z * vv1.z + ot[1].w * vv1.w; \
        dd += __shfl_xor_sync(FULLMASK, dd, 1); \
        dd += __shfl_xor_sync(FULLMASK, dd, 2); \
        dd += __shfl_xor_sync(FULLMASK, dd, 4); \
        if (l8 == 0) o[d] = dd; }
        PDOT(pv0, po0)
        PDOT(pv1, po1)
        PDOT(pv2, po2)
        PDOT(pv3, po3)
#undef PDOT
        // ---- hs epilogue ----
        if (Wn0) {
            for (int p = 0; p < 2; p++) {
                const float* Wn = p ? Wn1 : Wn0;
                float* hsO = p ? hsOut1 : hsOut0;
                const float4* Wn4 = (const float4*)Wn;
                __syncthreads();
                for (int i = tid; i < 1024; i += 512) {
                    float4 v = Wn4[i];
                    int r = i >> 4, c = (i & 15) * 4;
                    Wsh[r][c] = v.x; Wsh[r][c + 1] = v.y; Wsh[r][c + 2] = v.z; Wsh[r][c + 3] = v.w;
                }
                __syncthreads();
                float ea[2][4] = {};
                #pragma unroll
                for (int k = 0; k < 64; k++) {
                    float4 wv = *(const float4*)&Wsh[k][c0];
                    float x0 = Zs[r0 * 68 + k], x1 = Zs[(r0 + 1) * 68 + k];
                    ea[0][0] = fmaf(x0, wv.x, ea[0][0]); ea[0][1] = fmaf(x0, wv.y, ea[0][1]);
                    ea[0][2] = fmaf(x0, wv.z, ea[0][2]); ea[0][3] = fmaf(x0, wv.w, ea[0][3]);
                    ea[1][0] = fmaf(x1, wv.x, ea[1][0]); ea[1][1] = fmaf(x1, wv.y, ea[1][1]);
                    ea[1][2] = fmaf(x1, wv.z, ea[1][2]); ea[1][3] = fmaf(x1, wv.w, ea[1][3]);
                }
                #pragma unroll
                for (int i = 0; i < 2; i++)
                    *(float4*)&hsO[((size_t)(row0 + r0 + i)) * 64 + c0] =
                        make_float4(ea[i][0], ea[i][1], ea[i][2], ea[i][3]);
            }
        }
    } else {
        // ---------------- tf-part: 4 lanes/row, interleaved gather ----------------
        int tfIdx = blockIdx.x - npBlocks;
        bool isA = tfIdx < ntfA;
        int row0 = (isA ? tfIdx : tfIdx - ntfA) * 128;
        const int* rp = isA ? rpA : rpB;
        const int* cs = isA ? csA : csB;
        const float* ss = isA ? ssA : ssB;
        const float* sd = isA ? sdA : sdB;
        const float* hs = isA ? hsA : hsB;
        const float* b = isA ? bA : bB;
        float* Y = isA ? YA : YB;
        const float* v0 = isA ? vA0 : vB0;  float* o0 = isA ? oA0 : oB0;
        const float* v1 = isA ? vA1 : vB1;  float* o1 = isA ? oA1 : oB1;

        int g = tid >> 2, gl = tid & 3;
        int d = row0 + g;
        int beg = rp[d], end = rp[d + 1];
        float sdv = sd[d];
        float s = 0.f;
        float4 a0 = {0,0,0,0}, a1 = {0,0,0,0}, a2 = {0,0,0,0}, a3 = {0,0,0,0};
        const float4* H4 = (const float4*)hs;
        #pragma unroll 2
        for (int j = beg; j < end; j++) {
            int src = cs[j];
            float t = ss[src] + sdv;
            t = t > 0.f ? t : 0.2f * t;
            float ex = __expf(t);
            s += ex;
            size_t hb = (size_t)src * 16 + gl;     // interleaved
            float4 h0 = H4[hb], h1 = H4[hb + 4], h2 = H4[hb + 8], h3 = H4[hb + 12];
            a0.x = fmaf(ex, h0.x, a0.x); a0.y = fmaf(ex, h0.y, a0.y);
            a0.z = fmaf(ex, h0.z, a0.z); a0.w = fmaf(ex, h0.w, a0.w);
            a1.x = fmaf(ex, h1.x, a1.x); a1.y = fmaf(ex, h1.y, a1.y);
            a1.z = fmaf(ex, h1.z, a1.z); a1.w = fmaf(ex, h1.w, a1.w);
            a2.x = fmaf(ex, h2.x, a2.x); a2.y = fmaf(ex, h2.y, a2.y);
            a2.z = fmaf(ex, h2.z, a2.z); a2.w = fmaf(ex, h2.w, a2.w);
            a3.x = fmaf(ex, h3.x, a3.x); a3.y = fmaf(ex, h3.y, a3.y);
            a3.z = fmaf(ex, h3.z, a3.z); a3.w = fmaf(ex, h3.w, a3.w);
        }
        float inv = s > 0.f ? 1.f / s : 0.f;
        const float4* B4 = (const float4*)b;
        float4 bb0 = B4[gl], bb1 = B4[4 + gl], bb2 = B4[8 + gl], bb3 = B4[12 + gl];
        float4 ot[4];
        ot[0] = make_float4(a0.x * inv + bb0.x, a0.y * inv + bb0.y, a0.z * inv + bb0.z, a0.w * inv + bb0.w);
        ot[1] = make_float4(a1.x * inv + bb1.x, a1.y * inv + bb1.y, a1.z * inv + bb1.z, a1.w * inv + bb1.w);
        ot[2] = make_float4(a2.x * inv + bb2.x, a2.y * inv + bb2.y, a2.z * inv + bb2.z, a2.w * inv + bb2.w);
        ot[3] = make_float4(a3.x * inv + bb3.x, a3.y * inv + bb3.y, a3.z * inv + bb3.z, a3.w * inv + bb3.w);
        if (relu) {
            #pragma unroll
            for (int q = 0; q < 4; q++) {
                ot[q].x = fmaxf(ot[q].x, 0.f); ot[q].y = fmaxf(ot[q].y, 0.f);
                ot[q].z = fmaxf(ot[q].z, 0.f); ot[q].w = fmaxf(ot[q].w, 0.f);
            }
        }
        float4* Yr = (float4*)&Y[(size_t)d * 64];
        #pragma unroll
        for (int q = 0; q < 4; q++) Yr[q * 4 + gl] = ot[q];
#define TDOT(v, o) { \
        const float4* V4 = (const float4*)v; \
        float dd = 0.f; \
        _Pragma("unroll") \
        for (int q = 0; q < 4; q++) { \
            float4 vv = V4[q * 4 + gl]; \
            dd += ot[q].x * vv.x + ot[q].y * vv.y + ot[q].z * vv.z + ot[q].w * vv.w; \
        } \
        dd += __shfl_xor_sync(FULLMASK, dd, 1); \
        dd += __shfl_xor_sync(FULLMASK, dd, 2); \
        if (gl == 0) o[d] = dd; }
        TDOT(v0, o0)
        TDOT(v1, o1)
#undef TDOT
    }
}

// ---------------- fused pooling: 3 tables in one launch ----------------
__global__ void pool3(const float* __restrict__ xp, const float* __restrict__ xt,
                      const float* __restrict__ xf, float* __restrict__ rep) {
    int which = blockIdx.y;
    const float* x = (which == 0) ? xp : (which == 1) ? xt : xf;
    int npg = (which == 0) ? 64 : 512;
    int off = which * 192;
    int b = blockIdx.x;
    int t = threadIdx.x;            // 256
    int d = t & 63, c = t >> 6;
    const float* base = x + (size_t)b * npg * 64;
    float mx = -1e30f, mn = 1e30f, sm = 0.f;
    for (int n = c; n < npg; n += 4) {
        float v = base[(size_t)n * 64 + d];
        mx = fmaxf(mx, v); mn = fminf(mn, v); sm += v;
    }
    __shared__ float smx[4][64], smn[4][64], ssm[4][64];
    smx[c][d] = mx; smn[c][d] = mn; ssm[c][d] = sm;
    __syncthreads();
    if (c == 0) {
        for (int i = 1; i < 4; i++) {
            mx = fmaxf(mx, smx[i][d]); mn = fminf(mn, smn[i][d]); sm += ssm[i][d];
        }
        rep[b * 576 + off + d] = mx;
        rep[b * 576 + off + 64 + d] = mn;
        rep[b * 576 + off + 128 + d] = sm / (float)npg;
    }
}

// ---------------- fused actor head ----------------
__global__ void actor_head(const float* __restrict__ ap, const float* __restrict__ g,
                           const float* __restrict__ be, const float* __restrict__ Wa,
                           const float* __restrict__ ba, const int* __restrict__ part_id,
                           float* __restrict__ out) {
    __shared__ float sh[2];
    __shared__ float wa_s[128], g_s[64], be_s[64];
    int b = blockIdx.x, t = threadIdx.x;      // 64
    if (t < 64) {
        g_s[t] = g[t]; be_s[t] = be[t];
        wa_s[2 * t] = Wa[2 * t]; wa_s[2 * t + 1] = Wa[2 * t + 1];
    }
    __syncthreads();
    int n = b * 64 + t;
    const float4* A4 = (const float4*)&ap[(size_t)n * 64];
    float4 va[16];
    float sum = 0.f;
    #pragma unroll
    for (int q = 0; q < 16; q++) { va[q] = A4[q]; sum += va[q].x + va[q].y + va[q].z + va[q].w; }
    float mu = sum * (1.f / 64.f);
    float vs = 0.f;
    #pragma unroll
    for (int q = 0; q < 16; q++) {
        float dx = va[q].x - mu, dy = va[q].y - mu, dz = va[q].z - mu, dw = va[q].w - mu;
        vs += dx * dx + dy * dy + dz * dz + dw * dw;
    }
    float rs = rsqrtf(vs * (1.f / 64.f) + 1e-5f);
    float r0 = 0.f, r1 = 0.f;
    #pragma unroll
    for (int q = 0; q < 16; q++) {
        float y0 = (va[q].x - mu) * rs * g_s[4 * q]     + be_s[4 * q];
        float y1 = (va[q].y - mu) * rs * g_s[4 * q + 1] + be_s[4 * q + 1];
        float y2 = (va[q].z - mu) * rs * g_s[4 * q + 2] + be_s[4 * q + 2];
        float y3 = (va[q].w - mu) * rs * g_s[4 * q + 3] + be_s[4 * q + 3];
        r0 += y0 * wa_s[(4 * q) * 2] + y1 * wa_s[(4 * q + 1) * 2]
            + y2 * wa_s[(4 * q + 2) * 2] + y3 * wa_s[(4 * q + 3) * 2];
        r1 += y0 * wa_s[(4 * q) * 2 + 1] + y1 * wa_s[(4 * q + 1) * 2 + 1]
            + y2 * wa_s[(4 * q + 2) * 2 + 1] + y3 * wa_s[(4 * q + 3) * 2 + 1];
    }
    r0 += ba[0]; r1 += ba[1];
    float v = r0;
    for (int o = 16; o; o >>= 1) v = fmaxf(v, __shfl_xor_sync(FULLMASK, v, o));
    if ((t & 31) == 0) sh[t >> 5] = v;
    __syncthreads();
    float m0 = fmaxf(sh[0], sh[1]);
    __syncthreads();
    v = r1;
    for (int o = 16; o; o >>= 1) v = fmaxf(v, __shfl_xor_sync(FULLMASK, v, o));
    if ((t & 31) == 0) sh[t >> 5] = v;
    __syncthreads();
    float m1 = fmaxf(sh[0], sh[1]);
    __syncthreads();
    float e0 = expf(r0 - m0), e1 = expf(r1 - m1);
    v = e0;
    for (int o = 16; o; o >>= 1) v += __shfl_xor_sync(FULLMASK, v, o);
    if ((t & 31) == 0) sh[t >> 5] = v;
    __syncthreads();
    float s0 = sh[0] + sh[1];
    __syncthreads();
    v = e1;
    for (int o = 16; o; o >>= 1) v += __shfl_xor_sync(FULLMASK, v, o);
    if ((t & 31) == 0) sh[t >> 5] = v;
    __syncthreads();
    float s1 = sh[0] + sh[1];
    int p = part_id[n];
    out[b * 128 + p] = e0 / s0;
    out[b * 128 + 64 + p] = e1 / s1;
}

// ---------------- fused value head ----------------
__global__ void vhead(const float* __restrict__ rep,
                      const float* __restrict__ W1, const float* __restrict__ b1,
                      const float* __restrict__ W2, const float* __restrict__ b2,
                      const float* __restrict__ Wo, const float* __restrict__ bo,
                      float* __restrict__ V) {
    __shared__ float s[576];
    __shared__ float h[64];
    __shared__ float sh[2];
    int b = blockIdx.x, j = threadIdx.x;      // 64
    for (int k = j; k < 576; k += 64) s[k] = rep[b * 576 + k];
    __syncthreads();
    float acc = b1[j];
    for (int k = 0; k < 576; k++) acc = fmaf(s[k], W1[k * 64 + j], acc);
    acc = 0.5f * acc * (1.f + erff(acc * 0.70710678118654752f));
    h[j] = acc;
    __syncthreads();
    float acc2 = b2[j];
    #pragma unroll 8
    for (int k = 0; k < 64; k++) acc2 = fmaf(h[k], W2[k * 64 + j], acc2);
    acc2 = 0.5f * acc2 * (1.f + erff(acc2 * 0.70710678118654752f));
    float part = acc2 * Wo[j];
    for (int o = 16; o; o >>= 1) part += __shfl_xor_sync(FULLMASK, part, o);
    if ((j & 31) == 0) sh[j >> 5] = part;
    __syncthreads();
    if (j == 0) V[b] = tanhf(sh[0] + sh[1] + bo[0]);
}

// ---------------- host ----------------
#define SYMF(p, s) do { void* _q; cudaGetSymbolAddress(&_q, s); p = (float*)_q; } while (0)
#define SYMI(p, s) do { void* _q; cudaGetSymbolAddress(&_q, s); p = (int*)_q; } while (0)

extern "C" void kernel_launch(void* const* d_in, const int* in_sizes, int n_in,
                              void* d_out, int out_size) {
    const float* mass      = (const float*)d_in[0];
    const int*   pstate    = (const int*)d_in[1];
    const float* torque_x  = (const float*)d_in[2];
    const float* force_x   = (const float*)d_in[3];
    const int* e_pt_src = (const int*)d_in[4];
    const int* e_pt_dst = (const int*)d_in[5];
    const int* e_tp_src = (const int*)d_in[6];
    const int* e_tp_dst = (const int*)d_in[7];
    const int* e_pf_src = (const int*)d_in[8];
    const int* e_pf_dst = (const int*)d_in[9];
    const int* e_fp_src = (const int*)d_in[10];
    const int* e_fp_dst = (const int*)d_in[11];
    const int* part_id  = (const int*)d_in[13];
    const float* embW   = (const float*)d_in[14];
    const float* embS   = (const float*)d_in[15];
    const float* W_src  = (const float*)d_in[16];
    const float* W_dst  = (const float*)d_in[17];
    const float* a_src  = (const float*)d_in[18];
    const float* a_dst  = (const float*)d_in[19];
    const float* b_conv = (const float*)d_in[20];
    const float* ln_g   = (const float*)d_in[21];
    const float* ln_b   = (const float*)d_in[22];
    const float* outaW  = (const float*)d_in[23];
    const float* outab  = (const float*)d_in[24];
    const float* innW   = (const float*)d_in[25];
    const float* innb   = (const float*)d_in[26];
    const float* fulW   = (const float*)d_in[27];
    const float* fulb   = (const float*)d_in[28];
    const float* outW   = (const float*)d_in[29];
    const float* outb   = (const float*)d_in[30];
    float* out = (float*)d_out;

    float *xp, *xt, *xf, *ap, *hs0, *hs1;
    float *ss_pt, *ss_pf, *sd_tp, *sd_fp, *ss_tp, *sd_pt, *ss_fp, *sd_pf;
    float *wsv, *wdv, *rep;
    int *rp_pt, *rp_pf, *rp_tp, *rp_fp, *cs_pt, *cs_tp, *cs_pf, *cs_fp, *cnt, *aux;
    SYMF(xp, g_xp); SYMF(xt, g_xt); SYMF(xf, g_xf); SYMF(ap, g_ap);
    SYMF(hs0, g_hs0); SYMF(hs1, g_hs1);
    SYMF(ss_pt, g_ss_pt); SYMF(ss_pf, g_ss_pf); SYMF(sd_tp, g_sd_tp); SYMF(sd_fp, g_sd_fp);
    SYMF(ss_tp, g_ss_tp); SYMF(sd_pt, g_sd_pt); SYMF(ss_fp, g_ss_fp); SYMF(sd_pf, g_sd_pf);
    SYMF(wsv, g_wsv); SYMF(wdv, g_wdv); SYMF(rep, g_rep);
    SYMI(rp_pt, g_rp_pt); SYMI(rp_pf, g_rp_pf); SYMI(rp_tp, g_rp_tp); SYMI(rp_fp, g_rp_fp);
    SYMI(cs_pt, g_cs_pt); SYMI(cs_tp, g_cs_tp); SYMI(cs_pf, g_cs_pf); SYMI(cs_fp, g_cs_fp);
    SYMI(cnt, g_cnt); SYMI(aux, g_aux);

    // batched CSR build (parallel 3-phase scan)
    zero4<<<(4 * NTC) / 256, 256>>>(cnt);
    { dim3 g(EC / 256, 4); hist4<<<g, 256>>>(e_pt_dst, e_tp_dst, e_pf_dst, e_fp_dst, cnt); }
    { dim3 g(128, 4); scanA<<<g, 1024>>>(cnt, rp_pt, rp_tp, rp_pf, rp_fp, aux); }
    scanB<<<1, 512>>>(aux);
    { dim3 g(128, 4); scanC<<<g, 1024>>>(cnt, rp_pt, rp_tp, rp_pf, rp_fp, aux); }
    { dim3 g(EC / 256, 4);
      scatter4<<<g, 256>>>(e_pt_src, e_pt_dst, e_tp_src, e_tp_dst,
                           e_pf_src, e_pf_dst, e_fp_src, e_fp_dst,
                           rp_pt, rp_tp, rp_pf, rp_fp, cnt,
                           cs_pt, cs_tp, cs_pf, cs_fp); }

    // score vectors; embed; layer-0 score dots; bootstrap hs (parity 0)
    vec_all<<<10, 256>>>(W_src, a_src, W_dst, a_dst, wsv, wdv);
    dot4<<<(NTC * 32) / 256, 256>>>(torque_x, NTC,
         wsv + 1 * 64, ss_tp, wdv + 0 * 64, sd_pt, nullptr, nullptr, nullptr, nullptr);
    dot4<<<(NFC * 32) / 256, 256>>>(force_x, NFC,
         wsv + 3 * 64, ss_fp, wdv + 2 * 64, sd_pf, nullptr, nullptr, nullptr, nullptr);
    embed_k<<<(NPC * 64) / 256, 256>>>(mass, pstate, embW, embS, xp);
    dot4<<<(NPC * 32) / 256, 256>>>(xp, NPC,
         wsv + 0 * 64, ss_pt, wsv + 2 * 64, ss_pf,
         wdv + 1 * 64, sd_tp, wdv + 3 * 64, sd_fp);
    mm_hs<<<2 * (NPC / 64), 256>>>(xp, W_src + 0 * 4096, hs0, W_src + 2 * 4096, hs1);

    for (int l = 0; l < 5; l++) {
        int ci = l & 1, ni = (l + 1) & 1;
        const float* xti = (l == 0) ? torque_x : xt + (size_t)ni * NTC * 64;
        const float* xfi = (l == 0) ? force_x  : xf + (size_t)ni * NFC * 64;
        float* xto = xt + (size_t)ci * NTC * 64;
        float* xfo = xf + (size_t)ci * NFC * 64;
        const float* Wl = W_src + (size_t)l * 4 * 4096;
        const float* bl = b_conv + (size_t)l * 4 * 64;
        int relu = (l < 3) ? 1 : 0;
        int actor = (l == 4);
        const float* nwsv = wsv + (size_t)(l + 1) * 4 * 64;
        const float* nwdv = wdv + (size_t)(l + 1) * 4 * 64;
        const float* c_ss_pt = ss_pt + ci * NPC;  float* n_ss_pt = ss_pt + ni * NPC;
        const float* c_ss_pf = ss_pf + ci * NPC;  float* n_ss_pf = ss_pf + ni * NPC;
        const float* c_sd_tp = sd_tp + ci * NPC;  float* n_sd_tp = sd_tp + ni * NPC;
        const float* c_sd_fp = sd_fp + ci * NPC;  float* n_sd_fp = sd_fp + ni * NPC;
        const float* c_ss_tp = ss_tp + ci * NTC;  float* n_ss_tp = ss_tp + ni * NTC;
        const float* c_sd_pt = sd_pt + ci * NTC;  float* n_sd_pt = sd_pt + ni * NTC;
        const float* c_ss_fp = ss_fp + ci * NFC;  float* n_ss_fp = ss_fp + ni * NFC;
        const float* c_sd_pf = sd_pf + ci * NFC;  float* n_sd_pf = sd_pf + ni * NFC;
        const float* hs0c = hs0 + (size_t)ci * NPC * 64;
        const float* hs1c = hs1 + (size_t)ci * NPC * 64;
        float* hs0n = hs0 + (size_t)ni * NPC * 64;
        float* hs1n = hs1 + (size_t)ni * NPC * 64;
        const float* Wnext = W_src + (size_t)(l + 1) * 4 * 4096;
        int doEpi = (l < 3);

        if (!actor) {
            mega<<<NPC / 64 + NTC / 128 + NFC / 128, 512>>>(
                NPC / 64, NTC / 128,
                rp_tp, cs_tp, c_ss_tp, c_sd_tp, xti, Wl + 1 * 4096,
                rp_fp, cs_fp, c_ss_fp, c_sd_fp, xfi, Wl + 3 * 4096,
                bl + 1 * 64, bl + 3 * 64, xp, relu,
                nwsv + 0 * 64, n_ss_pt, nwsv + 2 * 64, n_ss_pf,
                nwdv + 1 * 64, n_sd_tp, nwdv + 3 * 64, n_sd_fp,
                doEpi ? (Wnext + 0 * 4096) : nullptr, hs0n,
                doEpi ? (Wnext + 2 * 4096) : nullptr, hs1n,
                rp_pt, cs_pt, c_ss_pt, c_sd_pt, hs0c, bl + 0 * 64, xto,
                nwsv + 1 * 64, n_ss_tp, nwdv + 0 * 64, n_sd_pt,
                rp_pf, cs_pf, c_ss_pf, c_sd_pf, hs1c, bl + 2 * 64, xfo,
                nwsv + 3 * 64, n_ss_fp, nwdv + 2 * 64, n_sd_pf);
        } else {
            mega<<<NPC / 64, 512>>>(
                NPC / 64, 0,
                rp_tp, cs_tp, c_ss_tp, c_sd_tp, xti, Wl + 1 * 4096,
                rp_fp, cs_fp, c_ss_fp, c_sd_fp, xfi, Wl + 3 * 4096,
                bl + 1 * 64, bl + 3 * 64, ap, 0,
                nullptr, nullptr, nullptr, nullptr,
                nullptr, nullptr, nullptr, nullptr,
                nullptr, nullptr, nullptr, nullptr,
                nullptr, nullptr, nullptr, nullptr, nullptr, nullptr, nullptr,
                nullptr, nullptr, nullptr, nullptr,
                nullptr, nullptr, nullptr, nullptr, nullptr, nullptr, nullptr,
                nullptr, nullptr, nullptr, nullptr);
        }
    }

    // fused pooling: l=3 wrote xt/xf parity 1; xp in place
    { dim3 g(BC, 3); pool3<<<g, 256>>>(xp, xt + (size_t)NTC * 64, xf + (size_t)NFC * 64, rep); }

    // fused heads
    actor_head<<<BC, 64>>>(ap, ln_g, ln_b, outaW, outab, part_id, out);
    vhead<<<BC, 64>>>(rep, innW, innb, fulW, fulb, outW, outb, out + BC * 128);
}